// round 1
// baseline (speedup 1.0000x reference)
#include <cuda_runtime.h>

// SAM Vision Attention: B=1, H=W=64, N=4096, C=768, nh=12, hd=64
// Pipeline:
//   1) qkv_gemm:  x[4096,768] @ qkv_w[768,2304] + b  -> q,k,v [head][n][64] (k pre-scaled)
//   2) relh/relw: decomposed rel-pos tables -> g_relh/g_relw [head][n][64]
//   3) flash_attn: per (head, image-row) online-softmax attention, bias fused
//   4) proj_gemm: attn_out[4096,768] @ proj_w[768,768] + b -> d_out

#define NH 12
#define NQ 4096
#define HD 64
#define CDIM 768
#define SCALE 0.125f   // 64^-0.5

__device__ float g_q[NH * NQ * HD];
__device__ float g_k[NH * NQ * HD];   // pre-scaled by SCALE
__device__ float g_v[NH * NQ * HD];
__device__ float g_relh[NH * NQ * HD];
__device__ float g_relw[NH * NQ * HD];
__device__ float g_ao[NQ * CDIM];

// ---------------------------------------------------------------------------
// QKV GEMM: M=4096, N=2304, K=768. 128x128 block tile, BK=16, 8x8 per thread.
// Scatters output into g_q / g_k / g_v ([head][n][d]) with bias; k gets SCALE.
// ---------------------------------------------------------------------------
__global__ __launch_bounds__(256) void qkv_gemm(const float* __restrict__ X,
                                                const float* __restrict__ W,
                                                const float* __restrict__ bias) {
    __shared__ float As[16][128];   // [k][m] (transposed)
    __shared__ float Bs[16][128];   // [k][n]
    const int bm = blockIdx.y * 128;
    const int bn = blockIdx.x * 128;
    const int tid = threadIdx.x;
    const int tx = tid & 15, ty = tid >> 4;

    float acc[8][8];
#pragma unroll
    for (int i = 0; i < 8; i++)
#pragma unroll
        for (int j = 0; j < 8; j++) acc[i][j] = 0.f;

    for (int k0 = 0; k0 < 768; k0 += 16) {
#pragma unroll
        for (int it = 0; it < 2; it++) {
            int f = tid + it * 256;            // 0..511
            int row = f >> 2, kq = (f & 3) << 2;
            float4 va = *(const float4*)(X + (size_t)(bm + row) * 768 + k0 + kq);
            As[kq + 0][row] = va.x;
            As[kq + 1][row] = va.y;
            As[kq + 2][row] = va.z;
            As[kq + 3][row] = va.w;
            int kk = f >> 5, nq = (f & 31) << 2;
            float4 vb = *(const float4*)(W + (size_t)(k0 + kk) * 2304 + bn + nq);
            *(float4*)&Bs[kk][nq] = vb;
        }
        __syncthreads();
#pragma unroll
        for (int k = 0; k < 16; k++) {
            float a[8], b[8];
            *(float4*)&a[0] = *(const float4*)&As[k][ty * 8];
            *(float4*)&a[4] = *(const float4*)&As[k][ty * 8 + 4];
            *(float4*)&b[0] = *(const float4*)&Bs[k][tx * 8];
            *(float4*)&b[4] = *(const float4*)&Bs[k][tx * 8 + 4];
#pragma unroll
            for (int i = 0; i < 8; i++)
#pragma unroll
                for (int j = 0; j < 8; j++) acc[i][j] = fmaf(a[i], b[j], acc[i][j]);
        }
        __syncthreads();
    }

#pragma unroll
    for (int i = 0; i < 8; i++) {
        int row = bm + ty * 8 + i;
#pragma unroll
        for (int j = 0; j < 8; j++) {
            int col = bn + tx * 8 + j;
            float val = acc[i][j] + bias[col];
            int which = col / 768;
            int rem = col - which * 768;
            int head = rem >> 6;
            int d = rem & 63;
            size_t off = ((size_t)head * NQ + row) * HD + d;
            if (which == 0) g_q[off] = val;
            else if (which == 1) g_k[off] = val * SCALE;
            else g_v[off] = val;
        }
    }
}

// ---------------------------------------------------------------------------
// rel_h table: g_relh[head][qh*64+qw][kh] = sum_c q * rel_pos_h[qh-kh+63][c]
// one block per (qh, head)
// ---------------------------------------------------------------------------
__global__ __launch_bounds__(256) void relh_kernel(const float* __restrict__ rp) {
    __shared__ float Qs[64][64];   // [qw][c]
    __shared__ float Rs[64][64];   // [kh][c]
    const int qh = blockIdx.x, head = blockIdx.y;
    const int tid = threadIdx.x, tx = tid & 15, ty = tid >> 4;
    const size_t qbase = ((size_t)head * NQ + qh * 64) * HD;

    for (int idx = tid; idx < 4096; idx += 256) {
        int r = idx >> 6, c = idx & 63;
        Qs[r][c] = g_q[qbase + idx];
        Rs[r][c] = rp[(qh - r + 63) * 64 + c];   // r = kh
    }
    __syncthreads();

    float acc[4][4];
#pragma unroll
    for (int i = 0; i < 4; i++)
#pragma unroll
        for (int j = 0; j < 4; j++) acc[i][j] = 0.f;

    for (int c = 0; c < 64; c++) {
        float a[4], b[4];
#pragma unroll
        for (int i = 0; i < 4; i++) a[i] = Qs[ty * 4 + i][c];
#pragma unroll
        for (int j = 0; j < 4; j++) b[j] = Rs[tx * 4 + j][c];
#pragma unroll
        for (int i = 0; i < 4; i++)
#pragma unroll
            for (int j = 0; j < 4; j++) acc[i][j] = fmaf(a[i], b[j], acc[i][j]);
    }
#pragma unroll
    for (int i = 0; i < 4; i++)
#pragma unroll
        for (int j = 0; j < 4; j++)
            g_relh[qbase + (size_t)(ty * 4 + i) * 64 + (tx * 4 + j)] = acc[i][j];
}

// ---------------------------------------------------------------------------
// rel_w table: g_relw[head][qh*64+qw][kw] = sum_c q * rel_pos_w[qw-kw+63][c]
// ---------------------------------------------------------------------------
__global__ __launch_bounds__(256) void relw_kernel(const float* __restrict__ rp) {
    __shared__ float Qs[64][64];    // [qw][c]
    __shared__ float Rs[127][64];   // full rel_pos_w table
    const int qh = blockIdx.x, head = blockIdx.y;
    const int tid = threadIdx.x, tx = tid & 15, ty = tid >> 4;
    const size_t qbase = ((size_t)head * NQ + qh * 64) * HD;

    for (int idx = tid; idx < 4096; idx += 256) {
        int r = idx >> 6, c = idx & 63;
        Qs[r][c] = g_q[qbase + idx];
    }
    for (int idx = tid; idx < 127 * 64; idx += 256) {
        Rs[idx >> 6][idx & 63] = rp[idx];
    }
    __syncthreads();

    float acc[4][4];
#pragma unroll
    for (int i = 0; i < 4; i++)
#pragma unroll
        for (int j = 0; j < 4; j++) acc[i][j] = 0.f;

    for (int c = 0; c < 64; c++) {
        float a[4];
#pragma unroll
        for (int i = 0; i < 4; i++) a[i] = Qs[ty * 4 + i][c];
#pragma unroll
        for (int i = 0; i < 4; i++) {
            int qw = ty * 4 + i;
#pragma unroll
            for (int j = 0; j < 4; j++) {
                int kw = tx * 4 + j;
                acc[i][j] = fmaf(a[i], Rs[qw - kw + 63][c], acc[i][j]);
            }
        }
    }
#pragma unroll
    for (int i = 0; i < 4; i++)
#pragma unroll
        for (int j = 0; j < 4; j++)
            g_relw[qbase + (size_t)(ty * 4 + i) * 64 + (tx * 4 + j)] = acc[i][j];
}

// ---------------------------------------------------------------------------
// Flash attention: block = (head, qh image row) = 64 queries.
// Online softmax over 64 key tiles (each = one key image row), bias fused:
//   S[r][c] = q.k_scaled + rel_h[r][kh_tile] + rel_w[r][kw]
// O accumulated in registers (4x4 fragment / thread), rescaled per step.
// ---------------------------------------------------------------------------
__global__ __launch_bounds__(256) void flash_attn() {
    extern __shared__ float sm[];
    float* Qs = sm;                  // [64][68] transposed: Qs[d*68 + r]
    float* Ks = Qs + 64 * 68;        // [64][68] transposed: Ks[d*68 + kw]
    float* Vs = Ks + 64 * 68;        // [64][64] natural:    Vs[kw*64 + d]
    float* Ss = Vs + 64 * 64;        // [64][65] scores / probs
    float* RW = Ss + 64 * 65;        // [64][65] rel_w tile
    float* RH = RW + 64 * 65;        // [64]     rel_h column for this key tile
    float* mS = RH + 64;             // [64]
    float* lS = mS + 64;             // [64]
    float* aS = lS + 64;             // [64]

    const int qh = blockIdx.x, head = blockIdx.y;
    const int tid = threadIdx.x, tx = tid & 15, ty = tid >> 4;
    const size_t qbase = ((size_t)head * NQ + qh * 64) * HD;
    const size_t hbase = (size_t)head * NQ * HD;

    for (int idx = tid; idx < 4096; idx += 256) {
        int r = idx >> 6, d = idx & 63;
        Qs[d * 68 + r] = g_q[qbase + (size_t)r * 64 + d];
        RW[r * 65 + d] = g_relw[qbase + (size_t)r * 64 + d];   // d plays kw here
    }
    if (tid < 64) { mS[tid] = -1e30f; lS[tid] = 0.f; }

    float o[4][4];
#pragma unroll
    for (int i = 0; i < 4; i++)
#pragma unroll
        for (int j = 0; j < 4; j++) o[i][j] = 0.f;

    for (int kt = 0; kt < 64; kt++) {
        __syncthreads();   // previous Ss/Ks/Vs consumers done (also covers Q init)
        for (int idx = tid; idx < 4096; idx += 256) {
            int kw = idx >> 6, d = idx & 63;
            size_t g = hbase + ((size_t)kt * 64 + kw) * 64 + d;
            Ks[d * 68 + kw] = g_k[g];
            Vs[idx] = g_v[g];
        }
        if (tid < 64) RH[tid] = g_relh[qbase + (size_t)tid * 64 + kt];
        __syncthreads();

        // S = Q @ K^T (both stored d-major in smem)
        float s[4][4];
#pragma unroll
        for (int i = 0; i < 4; i++)
#pragma unroll
            for (int j = 0; j < 4; j++) s[i][j] = 0.f;
#pragma unroll 8
        for (int d = 0; d < 64; d++) {
            float4 a4 = *(const float4*)&Qs[d * 68 + ty * 4];
            float4 b4 = *(const float4*)&Ks[d * 68 + tx * 4];
            float a[4] = {a4.x, a4.y, a4.z, a4.w};
            float b[4] = {b4.x, b4.y, b4.z, b4.w};
#pragma unroll
            for (int i = 0; i < 4; i++)
#pragma unroll
                for (int j = 0; j < 4; j++) s[i][j] = fmaf(a[i], b[j], s[i][j]);
        }
#pragma unroll
        for (int i = 0; i < 4; i++) {
            int row = ty * 4 + i;
            float rh = RH[row];
#pragma unroll
            for (int j = 0; j < 4; j++)
                Ss[row * 65 + tx * 4 + j] = s[i][j] + rh + RW[row * 65 + tx * 4 + j];
        }
        __syncthreads();

        // online softmax: 4 lanes per row
        {
            int row = tid >> 2, seg = tid & 3;
            float* srow = &Ss[row * 65 + seg * 16];
            float mx = -1e30f;
#pragma unroll
            for (int c = 0; c < 16; c++) mx = fmaxf(mx, srow[c]);
            mx = fmaxf(mx, __shfl_xor_sync(0xffffffffu, mx, 1));
            mx = fmaxf(mx, __shfl_xor_sync(0xffffffffu, mx, 2));
            float mold = mS[row];
            float mnew = fmaxf(mold, mx);
            float sum = 0.f;
#pragma unroll
            for (int c = 0; c < 16; c++) {
                float p = __expf(srow[c] - mnew);
                srow[c] = p;
                sum += p;
            }
            sum += __shfl_xor_sync(0xffffffffu, sum, 1);
            sum += __shfl_xor_sync(0xffffffffu, sum, 2);
            if (seg == 0) {
                float al = __expf(mold - mnew);
                lS[row] = lS[row] * al + sum;
                mS[row] = mnew;
                aS[row] = al;
            }
        }
        __syncthreads();

        // rescale O and accumulate O += P @ V
#pragma unroll
        for (int i = 0; i < 4; i++) {
            float al = aS[ty * 4 + i];
#pragma unroll
            for (int j = 0; j < 4; j++) o[i][j] *= al;
        }
#pragma unroll 8
        for (int kk = 0; kk < 64; kk++) {
            float4 b4 = *(const float4*)&Vs[kk * 64 + tx * 4];
#pragma unroll
            for (int i = 0; i < 4; i++) {
                float p = Ss[(ty * 4 + i) * 65 + kk];
                o[i][0] = fmaf(p, b4.x, o[i][0]);
                o[i][1] = fmaf(p, b4.y, o[i][1]);
                o[i][2] = fmaf(p, b4.z, o[i][2]);
                o[i][3] = fmaf(p, b4.w, o[i][3]);
            }
        }
    }
    __syncthreads();

#pragma unroll
    for (int i = 0; i < 4; i++) {
        int r = ty * 4 + i;
        float inv = 1.f / lS[r];
#pragma unroll
        for (int j = 0; j < 4; j++)
            g_ao[(size_t)(qh * 64 + r) * CDIM + head * 64 + tx * 4 + j] = o[i][j] * inv;
    }
}

// ---------------------------------------------------------------------------
// Output projection: g_ao[4096,768] @ proj_w[768,768] + proj_b -> d_out
// ---------------------------------------------------------------------------
__global__ __launch_bounds__(256) void proj_gemm(const float* __restrict__ W,
                                                 const float* __restrict__ bias,
                                                 float* __restrict__ out) {
    __shared__ float As[16][128];
    __shared__ float Bs[16][128];
    const int bm = blockIdx.y * 128;
    const int bn = blockIdx.x * 128;
    const int tid = threadIdx.x;
    const int tx = tid & 15, ty = tid >> 4;

    float acc[8][8];
#pragma unroll
    for (int i = 0; i < 8; i++)
#pragma unroll
        for (int j = 0; j < 8; j++) acc[i][j] = 0.f;

    for (int k0 = 0; k0 < 768; k0 += 16) {
#pragma unroll
        for (int it = 0; it < 2; it++) {
            int f = tid + it * 256;
            int row = f >> 2, kq = (f & 3) << 2;
            float4 va = *(const float4*)(g_ao + (size_t)(bm + row) * 768 + k0 + kq);
            As[kq + 0][row] = va.x;
            As[kq + 1][row] = va.y;
            As[kq + 2][row] = va.z;
            As[kq + 3][row] = va.w;
            int kk = f >> 5, nq = (f & 31) << 2;
            float4 vb = *(const float4*)(W + (size_t)(k0 + kk) * 768 + bn + nq);
            *(float4*)&Bs[kk][nq] = vb;
        }
        __syncthreads();
#pragma unroll
        for (int k = 0; k < 16; k++) {
            float a[8], b[8];
            *(float4*)&a[0] = *(const float4*)&As[k][ty * 8];
            *(float4*)&a[4] = *(const float4*)&As[k][ty * 8 + 4];
            *(float4*)&b[0] = *(const float4*)&Bs[k][tx * 8];
            *(float4*)&b[4] = *(const float4*)&Bs[k][tx * 8 + 4];
#pragma unroll
            for (int i = 0; i < 8; i++)
#pragma unroll
                for (int j = 0; j < 8; j++) acc[i][j] = fmaf(a[i], b[j], acc[i][j]);
        }
        __syncthreads();
    }

#pragma unroll
    for (int i = 0; i < 8; i++) {
        int row = bm + ty * 8 + i;
#pragma unroll
        for (int j = 0; j < 8; j++) {
            int col = bn + tx * 8 + j;
            out[(size_t)row * 768 + col] = acc[i][j] + bias[col];
        }
    }
}

// ---------------------------------------------------------------------------
extern "C" void kernel_launch(void* const* d_in, const int* in_sizes, int n_in,
                              void* d_out, int out_size) {
    const float* x      = (const float*)d_in[0];
    const float* qkv_w  = (const float*)d_in[1];
    const float* qkv_b  = (const float*)d_in[2];
    const float* proj_w = (const float*)d_in[3];
    const float* proj_b = (const float*)d_in[4];
    const float* rph    = (const float*)d_in[5];
    const float* rpw    = (const float*)d_in[6];
    float* out = (float*)d_out;

    const int FLASH_SMEM = (64 * 68 * 2 + 64 * 64 + 64 * 65 * 2 + 64 * 4) * 4;  // 85504 B
    cudaFuncSetAttribute(flash_attn, cudaFuncAttributeMaxDynamicSharedMemorySize, FLASH_SMEM);

    qkv_gemm<<<dim3(18, 32), 256>>>(x, qkv_w, qkv_b);
    relh_kernel<<<dim3(64, 12), 256>>>(rph);
    relw_kernel<<<dim3(64, 12), 256>>>(rpw);
    flash_attn<<<dim3(64, 12), 256, FLASH_SMEM>>>();
    proj_gemm<<<dim3(6, 32), 256>>>(proj_w, proj_b, out);
}

// round 3
// speedup vs baseline: 2.2688x; 2.2688x over previous
#include <cuda_runtime.h>
#include <cuda_fp16.h>

// SAM Vision Attention: B=1, H=W=64, N=4096, C=768, nh=12, hd=64
// R3: flash attention on tensor cores (mma.sync m16n8k16 fp16 -> fp32)
//     (R2 resubmit with __floats2half2_rn arg fix)

#define NH 12
#define NQ 4096
#define HD 64
#define CDIM 768
#define SCALE 0.125f   // 64^-0.5, power of two -> exact in fp16

__device__ float g_q[NH * NQ * HD];          // fp32 q for rel tables
__device__ __half g_q16[NH * NQ * HD];
__device__ __half g_k16[NH * NQ * HD];       // pre-scaled by SCALE
__device__ __half g_v16[NH * NQ * HD];
__device__ float g_relh[NH * NQ * HD];
__device__ float g_relw[NH * NQ * HD];
__device__ float g_ao[NQ * CDIM];

// ---------------------------------------------------------------------------
// helpers
// ---------------------------------------------------------------------------
__device__ __forceinline__ void mma16816(float* c, const unsigned* a,
                                         unsigned b0, unsigned b1) {
    asm volatile(
        "mma.sync.aligned.m16n8k16.row.col.f32.f16.f16.f32 "
        "{%0,%1,%2,%3}, {%4,%5,%6,%7}, {%8,%9}, {%0,%1,%2,%3};\n"
        : "+f"(c[0]), "+f"(c[1]), "+f"(c[2]), "+f"(c[3])
        : "r"(a[0]), "r"(a[1]), "r"(a[2]), "r"(a[3]), "r"(b0), "r"(b1));
}

__device__ __forceinline__ unsigned f2h2(float x, float y) {
    __half2 h = __floats2half2_rn(x, y);
    return *(unsigned*)&h;
}

__device__ __forceinline__ void cp_async16(void* dst, const void* src) {
    unsigned d = (unsigned)__cvta_generic_to_shared(dst);
    asm volatile("cp.async.cg.shared.global [%0], [%1], 16;\n" :: "r"(d), "l"(src));
}
#define CP_COMMIT asm volatile("cp.async.commit_group;\n")
#define CP_WAIT(n) asm volatile("cp.async.wait_group %0;\n" :: "n"(n))

// ---------------------------------------------------------------------------
// QKV GEMM: M=4096, N=2304, K=768. fp32 SIMT. Epilogue writes fp32 q (for rel
// tables) plus fp16 q/k/v for the tensor-core attention; k folded with SCALE.
// ---------------------------------------------------------------------------
__global__ __launch_bounds__(256) void qkv_gemm(const float* __restrict__ X,
                                                const float* __restrict__ W,
                                                const float* __restrict__ bias) {
    __shared__ float As[16][128];
    __shared__ float Bs[16][128];
    const int bm = blockIdx.y * 128;
    const int bn = blockIdx.x * 128;
    const int tid = threadIdx.x;
    const int tx = tid & 15, ty = tid >> 4;

    float acc[8][8];
#pragma unroll
    for (int i = 0; i < 8; i++)
#pragma unroll
        for (int j = 0; j < 8; j++) acc[i][j] = 0.f;

    for (int k0 = 0; k0 < 768; k0 += 16) {
#pragma unroll
        for (int it = 0; it < 2; it++) {
            int f = tid + it * 256;
            int row = f >> 2, kq = (f & 3) << 2;
            float4 va = *(const float4*)(X + (size_t)(bm + row) * 768 + k0 + kq);
            As[kq + 0][row] = va.x;
            As[kq + 1][row] = va.y;
            As[kq + 2][row] = va.z;
            As[kq + 3][row] = va.w;
            int kk = f >> 5, nq = (f & 31) << 2;
            float4 vb = *(const float4*)(W + (size_t)(k0 + kk) * 2304 + bn + nq);
            *(float4*)&Bs[kk][nq] = vb;
        }
        __syncthreads();
#pragma unroll
        for (int k = 0; k < 16; k++) {
            float a[8], b[8];
            *(float4*)&a[0] = *(const float4*)&As[k][ty * 8];
            *(float4*)&a[4] = *(const float4*)&As[k][ty * 8 + 4];
            *(float4*)&b[0] = *(const float4*)&Bs[k][tx * 8];
            *(float4*)&b[4] = *(const float4*)&Bs[k][tx * 8 + 4];
#pragma unroll
            for (int i = 0; i < 8; i++)
#pragma unroll
                for (int j = 0; j < 8; j++) acc[i][j] = fmaf(a[i], b[j], acc[i][j]);
        }
        __syncthreads();
    }

#pragma unroll
    for (int i = 0; i < 8; i++) {
        int row = bm + ty * 8 + i;
#pragma unroll
        for (int j = 0; j < 8; j++) {
            int col = bn + tx * 8 + j;
            float val = acc[i][j] + bias[col];
            int which = col / 768;
            int rem = col - which * 768;
            int head = rem >> 6;
            int d = rem & 63;
            size_t off = ((size_t)head * NQ + row) * HD + d;
            if (which == 0) { g_q[off] = val; g_q16[off] = __float2half(val); }
            else if (which == 1) g_k16[off] = __float2half(val * SCALE);
            else g_v16[off] = __float2half(val);
        }
    }
}

// ---------------------------------------------------------------------------
// rel_h table (fp32)
// ---------------------------------------------------------------------------
__global__ __launch_bounds__(256) void relh_kernel(const float* __restrict__ rp) {
    __shared__ float Qs[64][64];
    __shared__ float Rs[64][64];
    const int qh = blockIdx.x, head = blockIdx.y;
    const int tid = threadIdx.x, tx = tid & 15, ty = tid >> 4;
    const size_t qbase = ((size_t)head * NQ + qh * 64) * HD;

    for (int idx = tid; idx < 4096; idx += 256) {
        int r = idx >> 6, c = idx & 63;
        Qs[r][c] = g_q[qbase + idx];
        Rs[r][c] = rp[(qh - r + 63) * 64 + c];
    }
    __syncthreads();

    float acc[4][4];
#pragma unroll
    for (int i = 0; i < 4; i++)
#pragma unroll
        for (int j = 0; j < 4; j++) acc[i][j] = 0.f;

    for (int c = 0; c < 64; c++) {
        float a[4], b[4];
#pragma unroll
        for (int i = 0; i < 4; i++) a[i] = Qs[ty * 4 + i][c];
#pragma unroll
        for (int j = 0; j < 4; j++) b[j] = Rs[tx * 4 + j][c];
#pragma unroll
        for (int i = 0; i < 4; i++)
#pragma unroll
            for (int j = 0; j < 4; j++) acc[i][j] = fmaf(a[i], b[j], acc[i][j]);
    }
#pragma unroll
    for (int i = 0; i < 4; i++)
#pragma unroll
        for (int j = 0; j < 4; j++)
            g_relh[qbase + (size_t)(ty * 4 + i) * 64 + (tx * 4 + j)] = acc[i][j];
}

// ---------------------------------------------------------------------------
// rel_w table (fp32)
// ---------------------------------------------------------------------------
__global__ __launch_bounds__(256) void relw_kernel(const float* __restrict__ rp) {
    __shared__ float Qs[64][64];
    __shared__ float Rs[127][64];
    const int qh = blockIdx.x, head = blockIdx.y;
    const int tid = threadIdx.x, tx = tid & 15, ty = tid >> 4;
    const size_t qbase = ((size_t)head * NQ + qh * 64) * HD;

    for (int idx = tid; idx < 4096; idx += 256) {
        int r = idx >> 6, c = idx & 63;
        Qs[r][c] = g_q[qbase + idx];
    }
    for (int idx = tid; idx < 127 * 64; idx += 256) {
        Rs[idx >> 6][idx & 63] = rp[idx];
    }
    __syncthreads();

    float acc[4][4];
#pragma unroll
    for (int i = 0; i < 4; i++)
#pragma unroll
        for (int j = 0; j < 4; j++) acc[i][j] = 0.f;

    for (int c = 0; c < 64; c++) {
        float a[4];
#pragma unroll
        for (int i = 0; i < 4; i++) a[i] = Qs[ty * 4 + i][c];
#pragma unroll
        for (int i = 0; i < 4; i++) {
            int qw = ty * 4 + i;
#pragma unroll
            for (int j = 0; j < 4; j++) {
                int kw = tx * 4 + j;
                acc[i][j] = fmaf(a[i], Rs[qw - kw + 63][c], acc[i][j]);
            }
        }
    }
#pragma unroll
    for (int i = 0; i < 4; i++)
#pragma unroll
        for (int j = 0; j < 4; j++)
            g_relw[qbase + (size_t)(ty * 4 + i) * 64 + (tx * 4 + j)] = acc[i][j];
}

// ---------------------------------------------------------------------------
// Tensor-core flash attention.
// Block = (qh, head): 64 queries. 4 warps x 16 rows. 64 key tiles of 64.
// S = Q16 @ K16^T via mma.m16n8k16 (fp32 accum), bias from fp16 smem tables,
// online softmax in registers, P repacked to A fragments, O += P @ V16.
// K/V tiles double-buffered via cp.async.
// smem (halves): Qs[64*72] | Ks[2][64*72] | Vs[2][64*72] | RW[64*72] | RH[64*72]
// ---------------------------------------------------------------------------
__global__ __launch_bounds__(128) void flash_attn() {
    extern __shared__ __half sm[];
    __half* Qs  = sm;                 // 4608
    __half* Ksh = sm + 4608;          // 2 x 4608
    __half* Vsh = sm + 13824;         // 2 x 4608
    __half* RWs = sm + 23040;         // 4608  [q][kw]
    __half* RHs = sm + 27648;         // 4608  [q][kh]

    const int qh = blockIdx.x, head = blockIdx.y;
    const int tid  = threadIdx.x;
    const int w    = tid >> 5;
    const int lane = tid & 31;
    const int g    = lane >> 2;
    const int t    = lane & 3;
    const int r0 = 16 * w + g;        // fragment rows (block-local query idx)
    const int r1 = r0 + 8;

    const size_t qbase = ((size_t)head * NQ + qh * 64) * HD;
    const size_t hbase = (size_t)head * NQ * HD;

    // ---- fill Q (fp16) and bias tables (fp32 -> fp16) ----
    {
        const unsigned* gq = (const unsigned*)(g_q16 + qbase);
        for (int i = tid; i < 2048; i += 128) {
            int r = i >> 5, c2 = i & 31;
            *(unsigned*)&Qs[r * 72 + c2 * 2] = gq[i];
        }
        for (int i = tid; i < 4096; i += 128) {
            int r = i >> 6, c = i & 63;
            RWs[r * 72 + c] = __float2half(g_relw[qbase + i]);
            RHs[r * 72 + c] = __float2half(g_relh[qbase + i]);
        }
    }

    // ---- prefetch key tile 0 ----
    {
        const __half* gk = g_k16 + hbase;
        const __half* gv = g_v16 + hbase;
#pragma unroll
        for (int i = 0; i < 4; i++) {
            int c = tid + i * 128;          // 0..511 chunks of 8 halves
            int key = c >> 3, off = (c & 7) * 8;
            cp_async16(&Ksh[key * 72 + off], gk + c * 8);
            cp_async16(&Vsh[key * 72 + off], gv + c * 8);
        }
        CP_COMMIT;
    }
    __syncthreads();

    // ---- Q fragments (registers, reused across all key tiles) ----
    unsigned qa[4][4];
#pragma unroll
    for (int u = 0; u < 4; u++) {
        int d = 16 * u + 2 * t;
        qa[u][0] = *(const unsigned*)&Qs[r0 * 72 + d];
        qa[u][1] = *(const unsigned*)&Qs[r1 * 72 + d];
        qa[u][2] = *(const unsigned*)&Qs[r0 * 72 + d + 8];
        qa[u][3] = *(const unsigned*)&Qs[r1 * 72 + d + 8];
    }

    float o[8][4];
#pragma unroll
    for (int j = 0; j < 8; j++)
#pragma unroll
        for (int e = 0; e < 4; e++) o[j][e] = 0.f;
    float m0 = -1e30f, m1 = -1e30f, l0 = 0.f, l1 = 0.f;

    for (int kt = 0; kt < 64; kt++) {
        const int cur = kt & 1;
        if (kt < 63) {
            const __half* gk = g_k16 + hbase + (size_t)(kt + 1) * 4096;
            const __half* gv = g_v16 + hbase + (size_t)(kt + 1) * 4096;
            __half* dk = Ksh + (cur ^ 1) * 4608;
            __half* dv = Vsh + (cur ^ 1) * 4608;
#pragma unroll
            for (int i = 0; i < 4; i++) {
                int c = tid + i * 128;
                int key = c >> 3, off = (c & 7) * 8;
                cp_async16(&dk[key * 72 + off], gk + c * 8);
                cp_async16(&dv[key * 72 + off], gv + c * 8);
            }
            CP_COMMIT;
            CP_WAIT(1);
        } else {
            CP_WAIT(0);
        }
        __syncthreads();

        const __half* K = Ksh + cur * 4608;
        const __half* V = Vsh + cur * 4608;

        // ---- S = Q @ K^T ----
        float c[8][4];
#pragma unroll
        for (int j = 0; j < 8; j++)
#pragma unroll
            for (int e = 0; e < 4; e++) c[j][e] = 0.f;
#pragma unroll
        for (int u = 0; u < 4; u++) {
            int d = 16 * u + 2 * t;
#pragma unroll
            for (int j = 0; j < 8; j++) {
                int key = 8 * j + g;
                unsigned b0 = *(const unsigned*)&K[key * 72 + d];
                unsigned b1 = *(const unsigned*)&K[key * 72 + d + 8];
                mma16816(c[j], qa[u], b0, b1);
            }
        }

        // ---- bias ----
        float rh0 = __half2float(RHs[r0 * 72 + kt]);
        float rh1 = __half2float(RHs[r1 * 72 + kt]);
#pragma unroll
        for (int j = 0; j < 8; j++) {
            int col = 8 * j + 2 * t;
            float2 w0 = __half22float2(*(const __half2*)&RWs[r0 * 72 + col]);
            float2 w1 = __half22float2(*(const __half2*)&RWs[r1 * 72 + col]);
            c[j][0] += rh0 + w0.x;
            c[j][1] += rh0 + w0.y;
            c[j][2] += rh1 + w1.x;
            c[j][3] += rh1 + w1.y;
        }

        // ---- online softmax (register-resident) ----
        float mx0 = -1e30f, mx1 = -1e30f;
#pragma unroll
        for (int j = 0; j < 8; j++) {
            mx0 = fmaxf(mx0, fmaxf(c[j][0], c[j][1]));
            mx1 = fmaxf(mx1, fmaxf(c[j][2], c[j][3]));
        }
        mx0 = fmaxf(mx0, __shfl_xor_sync(0xffffffffu, mx0, 1));
        mx0 = fmaxf(mx0, __shfl_xor_sync(0xffffffffu, mx0, 2));
        mx1 = fmaxf(mx1, __shfl_xor_sync(0xffffffffu, mx1, 1));
        mx1 = fmaxf(mx1, __shfl_xor_sync(0xffffffffu, mx1, 2));

        float mn0 = fmaxf(m0, mx0), mn1 = fmaxf(m1, mx1);
        float al0 = __expf(m0 - mn0), al1 = __expf(m1 - mn1);
        m0 = mn0; m1 = mn1;

        float s0 = 0.f, s1 = 0.f;
#pragma unroll
        for (int j = 0; j < 8; j++) {
            c[j][0] = __expf(c[j][0] - mn0); s0 += c[j][0];
            c[j][1] = __expf(c[j][1] - mn0); s0 += c[j][1];
            c[j][2] = __expf(c[j][2] - mn1); s1 += c[j][2];
            c[j][3] = __expf(c[j][3] - mn1); s1 += c[j][3];
        }
        s0 += __shfl_xor_sync(0xffffffffu, s0, 1);
        s0 += __shfl_xor_sync(0xffffffffu, s0, 2);
        s1 += __shfl_xor_sync(0xffffffffu, s1, 1);
        s1 += __shfl_xor_sync(0xffffffffu, s1, 2);
        l0 = l0 * al0 + s0;
        l1 = l1 * al1 + s1;

#pragma unroll
        for (int j = 0; j < 8; j++) {
            o[j][0] *= al0; o[j][1] *= al0;
            o[j][2] *= al1; o[j][3] *= al1;
        }

        // ---- O += P @ V ----
        const unsigned short* Vu = (const unsigned short*)V;
#pragma unroll
        for (int u = 0; u < 4; u++) {
            unsigned pa[4];
            pa[0] = f2h2(c[2 * u][0], c[2 * u][1]);
            pa[1] = f2h2(c[2 * u][2], c[2 * u][3]);
            pa[2] = f2h2(c[2 * u + 1][0], c[2 * u + 1][1]);
            pa[3] = f2h2(c[2 * u + 1][2], c[2 * u + 1][3]);
            int kr = 16 * u + 2 * t;
#pragma unroll
            for (int j = 0; j < 8; j++) {
                int col = 8 * j + g;
                unsigned v0 = Vu[(kr)     * 72 + col];
                unsigned v1 = Vu[(kr + 1) * 72 + col];
                unsigned v2 = Vu[(kr + 8) * 72 + col];
                unsigned v3 = Vu[(kr + 9) * 72 + col];
                mma16816(o[j], pa, v0 | (v1 << 16), v2 | (v3 << 16));
            }
        }
        __syncthreads();   // all warps done with buffer `cur` before refill
    }

    // ---- normalize + write ----
    float inv0 = 1.f / l0, inv1 = 1.f / l1;
    float* outp = g_ao + (size_t)(qh * 64) * CDIM + head * 64;
#pragma unroll
    for (int j = 0; j < 8; j++) {
        int col = 8 * j + 2 * t;
        float2 y0 = make_float2(o[j][0] * inv0, o[j][1] * inv0);
        float2 y1 = make_float2(o[j][2] * inv1, o[j][3] * inv1);
        *(float2*)&outp[(size_t)r0 * CDIM + col] = y0;
        *(float2*)&outp[(size_t)r1 * CDIM + col] = y1;
    }
}

// ---------------------------------------------------------------------------
// Output projection (fp32 SIMT)
// ---------------------------------------------------------------------------
__global__ __launch_bounds__(256) void proj_gemm(const float* __restrict__ W,
                                                 const float* __restrict__ bias,
                                                 float* __restrict__ out) {
    __shared__ float As[16][128];
    __shared__ float Bs[16][128];
    const int bm = blockIdx.y * 128;
    const int bn = blockIdx.x * 128;
    const int tid = threadIdx.x;
    const int tx = tid & 15, ty = tid >> 4;

    float acc[8][8];
#pragma unroll
    for (int i = 0; i < 8; i++)
#pragma unroll
        for (int j = 0; j < 8; j++) acc[i][j] = 0.f;

    for (int k0 = 0; k0 < 768; k0 += 16) {
#pragma unroll
        for (int it = 0; it < 2; it++) {
            int f = tid + it * 256;
            int row = f >> 2, kq = (f & 3) << 2;
            float4 va = *(const float4*)(g_ao + (size_t)(bm + row) * 768 + k0 + kq);
            As[kq + 0][row] = va.x;
            As[kq + 1][row] = va.y;
            As[kq + 2][row] = va.z;
            As[kq + 3][row] = va.w;
            int kk = f >> 5, nq = (f & 31) << 2;
            float4 vb = *(const float4*)(W + (size_t)(k0 + kk) * 768 + bn + nq);
            *(float4*)&Bs[kk][nq] = vb;
        }
        __syncthreads();
#pragma unroll
        for (int k = 0; k < 16; k++) {
            float a[8], b[8];
            *(float4*)&a[0] = *(const float4*)&As[k][ty * 8];
            *(float4*)&a[4] = *(const float4*)&As[k][ty * 8 + 4];
            *(float4*)&b[0] = *(const float4*)&Bs[k][tx * 8];
            *(float4*)&b[4] = *(const float4*)&Bs[k][tx * 8 + 4];
#pragma unroll
            for (int i = 0; i < 8; i++)
#pragma unroll
                for (int j = 0; j < 8; j++) acc[i][j] = fmaf(a[i], b[j], acc[i][j]);
        }
        __syncthreads();
    }

#pragma unroll
    for (int i = 0; i < 8; i++) {
        int row = bm + ty * 8 + i;
#pragma unroll
        for (int j = 0; j < 8; j++) {
            int col = bn + tx * 8 + j;
            out[(size_t)row * 768 + col] = acc[i][j] + bias[col];
        }
    }
}

// ---------------------------------------------------------------------------
extern "C" void kernel_launch(void* const* d_in, const int* in_sizes, int n_in,
                              void* d_out, int out_size) {
    const float* x      = (const float*)d_in[0];
    const float* qkv_w  = (const float*)d_in[1];
    const float* qkv_b  = (const float*)d_in[2];
    const float* proj_w = (const float*)d_in[3];
    const float* proj_b = (const float*)d_in[4];
    const float* rph    = (const float*)d_in[5];
    const float* rpw    = (const float*)d_in[6];
    float* out = (float*)d_out;

    const int FLASH_SMEM = 32256 * 2;   // 64512 B of half
    cudaFuncSetAttribute(flash_attn, cudaFuncAttributeMaxDynamicSharedMemorySize, FLASH_SMEM);

    qkv_gemm<<<dim3(18, 32), 256>>>(x, qkv_w, qkv_b);
    relh_kernel<<<dim3(64, 12), 256>>>(rph);
    relw_kernel<<<dim3(64, 12), 256>>>(rpw);
    flash_attn<<<dim3(64, 12), 128, FLASH_SMEM>>>();
    proj_gemm<<<dim3(6, 32), 256>>>(proj_w, proj_b, out);
}

// round 5
// speedup vs baseline: 2.9525x; 1.3013x over previous
#include <cuda_runtime.h>
#include <cuda_fp16.h>

// SAM Vision Attention: B=1, H=W=64, N=4096, C=768, nh=12, hd=64
// R5: fp16 HMMA for qkv/proj with in-kernel fp32->fp16 tile loading
//     (no pre-transpose kernels, no cp.async in GEMMs, dynamic smem).
//     flash_attn / rel kernels unchanged from the validated R3/R4 code.

#define NH 12
#define NQ 4096
#define HD 64
#define CDIM 768
#define SCALE 0.125f   // 64^-0.5, exact in fp16

__device__ float  g_q[NH * NQ * HD];          // fp32 q for rel tables
__device__ __half g_q16[NH * NQ * HD];
__device__ __half g_k16[NH * NQ * HD];        // pre-scaled by SCALE
__device__ __half g_v16[NH * NQ * HD];
__device__ float  g_relh[NH * NQ * HD];
__device__ float  g_relw[NH * NQ * HD];
__device__ __half g_ao16[NQ * CDIM];          // attention output (proj A input)

// ---------------------------------------------------------------------------
// helpers
// ---------------------------------------------------------------------------
__device__ __forceinline__ void mma16816(float* c, const unsigned* a,
                                         unsigned b0, unsigned b1) {
    asm volatile(
        "mma.sync.aligned.m16n8k16.row.col.f32.f16.f16.f32 "
        "{%0,%1,%2,%3}, {%4,%5,%6,%7}, {%8,%9}, {%0,%1,%2,%3};\n"
        : "+f"(c[0]), "+f"(c[1]), "+f"(c[2]), "+f"(c[3])
        : "r"(a[0]), "r"(a[1]), "r"(a[2]), "r"(a[3]), "r"(b0), "r"(b1));
}

__device__ __forceinline__ unsigned f2h2(float x, float y) {
    __half2 h = __floats2half2_rn(x, y);
    return *(unsigned*)&h;
}

__device__ __forceinline__ void cp_async16(void* dst, const void* src) {
    unsigned d = (unsigned)__cvta_generic_to_shared(dst);
    asm volatile("cp.async.cg.shared.global [%0], [%1], 16;\n" :: "r"(d), "l"(src));
}
#define CP_COMMIT asm volatile("cp.async.commit_group;\n")
#define CP_WAIT(n) asm volatile("cp.async.wait_group %0;\n" :: "n"(n))

// ---------------------------------------------------------------------------
// QKV GEMM (fp16 HMMA): M=4096, N=2304, K=768, BM=BN=128, BK=32, 8 warps.
// Loads fp32 x / qkv_w tiles directly, converts to fp16 in registers.
// Epilogue scatters q (fp32 + fp16) / k (scaled) / v.
// smem layout (halves): As [128][40] | Bs [128][40]  (Bs is n-major)
// ---------------------------------------------------------------------------
__global__ __launch_bounds__(256) void qkv_hgemm(const float* __restrict__ X,
                                                 const float* __restrict__ W,
                                                 const float* __restrict__ bias) {
    extern __shared__ __half smq[];
    __half* As = smq;           // 5120 halves
    __half* Bs = smq + 5120;    // 5120 halves

    const int bm = blockIdx.y * 128, bn = blockIdx.x * 128;
    const int tid = threadIdx.x;
    const int w = tid >> 5, lane = tid & 31;
    const int g = lane >> 2, t = lane & 3;
    const int m0 = (w >> 1) * 32, n0 = (w & 1) * 64;

    float acc[2][8][4];
#pragma unroll
    for (int mi = 0; mi < 2; mi++)
#pragma unroll
        for (int nj = 0; nj < 8; nj++)
#pragma unroll
            for (int e = 0; e < 4; e++) acc[mi][nj][e] = 0.f;

    for (int kt = 0; kt < 24; kt++) {
        const int k0 = kt * 32;
        // A: x[bm+row][k0 .. k0+32) -> As[row][0..32)
#pragma unroll
        for (int i = 0; i < 4; i++) {
            int cdx = tid + i * 256;                 // 0..1023
            int row = cdx >> 3, off4 = (cdx & 7) * 4;
            float4 v = *(const float4*)(X + (size_t)(bm + row) * 768 + k0 + off4);
            *(__half2*)&As[row * 40 + off4]     = __floats2half2_rn(v.x, v.y);
            *(__half2*)&As[row * 40 + off4 + 2] = __floats2half2_rn(v.z, v.w);
        }
        // B: W[k0+kk][bn+n] -> Bs[n][kk] (transposed on store)
#pragma unroll
        for (int i = 0; i < 4; i++) {
            int cdx = tid + i * 256;                 // 0..1023
            int kk = cdx >> 5, n4 = (cdx & 31) * 4;
            float4 v = *(const float4*)(W + (size_t)(k0 + kk) * 2304 + bn + n4);
            Bs[(n4 + 0) * 40 + kk] = __float2half(v.x);
            Bs[(n4 + 1) * 40 + kk] = __float2half(v.y);
            Bs[(n4 + 2) * 40 + kk] = __float2half(v.z);
            Bs[(n4 + 3) * 40 + kk] = __float2half(v.w);
        }
        __syncthreads();

#pragma unroll
        for (int ks = 0; ks < 2; ks++) {
            unsigned a[2][4], b[8][2];
#pragma unroll
            for (int mi = 0; mi < 2; mi++) {
                int row = m0 + mi * 16 + g;
                int kk = ks * 16 + 2 * t;
                a[mi][0] = *(const unsigned*)&As[row * 40 + kk];
                a[mi][1] = *(const unsigned*)&As[(row + 8) * 40 + kk];
                a[mi][2] = *(const unsigned*)&As[row * 40 + kk + 8];
                a[mi][3] = *(const unsigned*)&As[(row + 8) * 40 + kk + 8];
            }
#pragma unroll
            for (int nj = 0; nj < 8; nj++) {
                int col = n0 + nj * 8 + g;
                int kk = ks * 16 + 2 * t;
                b[nj][0] = *(const unsigned*)&Bs[col * 40 + kk];
                b[nj][1] = *(const unsigned*)&Bs[col * 40 + kk + 8];
            }
#pragma unroll
            for (int mi = 0; mi < 2; mi++)
#pragma unroll
                for (int nj = 0; nj < 8; nj++)
                    mma16816(acc[mi][nj], a[mi], b[nj][0], b[nj][1]);
        }
        __syncthreads();
    }

#pragma unroll
    for (int mi = 0; mi < 2; mi++)
#pragma unroll
        for (int nj = 0; nj < 8; nj++)
#pragma unroll
            for (int e = 0; e < 4; e++) {
                int row = bm + m0 + mi * 16 + g + (e >> 1) * 8;
                int col = bn + n0 + nj * 8 + 2 * t + (e & 1);
                float val = acc[mi][nj][e] + bias[col];
                int which = col / 768;
                int rem = col - which * 768;
                int head = rem >> 6, d = rem & 63;
                size_t off = ((size_t)head * NQ + row) * HD + d;
                if (which == 0) { g_q[off] = val; g_q16[off] = __float2half(val); }
                else if (which == 1) g_k16[off] = __float2half(val * SCALE);
                else g_v16[off] = __float2half(val);
            }
}

// ---------------------------------------------------------------------------
// proj GEMM (fp16 HMMA): M=4096, N=768. A = g_ao16 (fp16), W = proj_w (fp32).
// ---------------------------------------------------------------------------
__global__ __launch_bounds__(256) void proj_hgemm(const float* __restrict__ W,
                                                  const float* __restrict__ bias,
                                                  float* __restrict__ out) {
    extern __shared__ __half smp[];
    __half* As = smp;
    __half* Bs = smp + 5120;

    const int bm = blockIdx.y * 128, bn = blockIdx.x * 128;
    const int tid = threadIdx.x;
    const int w = tid >> 5, lane = tid & 31;
    const int g = lane >> 2, t = lane & 3;
    const int m0 = (w >> 1) * 32, n0 = (w & 1) * 64;

    float acc[2][8][4];
#pragma unroll
    for (int mi = 0; mi < 2; mi++)
#pragma unroll
        for (int nj = 0; nj < 8; nj++)
#pragma unroll
            for (int e = 0; e < 4; e++) acc[mi][nj][e] = 0.f;

    for (int kt = 0; kt < 24; kt++) {
        const int k0 = kt * 32;
        // A: g_ao16[bm+row][k0..k0+32) fp16, 8 halves per chunk
#pragma unroll
        for (int i = 0; i < 2; i++) {
            int cdx = tid + i * 256;                 // 0..511
            int row = cdx >> 2, off8 = (cdx & 3) * 8;
            *(uint4*)&As[row * 40 + off8] =
                *(const uint4*)(g_ao16 + (size_t)(bm + row) * 768 + k0 + off8);
        }
        // B: proj_w[k0+kk][bn+n] fp32 -> Bs[n][kk]
#pragma unroll
        for (int i = 0; i < 4; i++) {
            int cdx = tid + i * 256;
            int kk = cdx >> 5, n4 = (cdx & 31) * 4;
            float4 v = *(const float4*)(W + (size_t)(k0 + kk) * 768 + bn + n4);
            Bs[(n4 + 0) * 40 + kk] = __float2half(v.x);
            Bs[(n4 + 1) * 40 + kk] = __float2half(v.y);
            Bs[(n4 + 2) * 40 + kk] = __float2half(v.z);
            Bs[(n4 + 3) * 40 + kk] = __float2half(v.w);
        }
        __syncthreads();

#pragma unroll
        for (int ks = 0; ks < 2; ks++) {
            unsigned a[2][4], b[8][2];
#pragma unroll
            for (int mi = 0; mi < 2; mi++) {
                int row = m0 + mi * 16 + g;
                int kk = ks * 16 + 2 * t;
                a[mi][0] = *(const unsigned*)&As[row * 40 + kk];
                a[mi][1] = *(const unsigned*)&As[(row + 8) * 40 + kk];
                a[mi][2] = *(const unsigned*)&As[row * 40 + kk + 8];
                a[mi][3] = *(const unsigned*)&As[(row + 8) * 40 + kk + 8];
            }
#pragma unroll
            for (int nj = 0; nj < 8; nj++) {
                int col = n0 + nj * 8 + g;
                int kk = ks * 16 + 2 * t;
                b[nj][0] = *(const unsigned*)&Bs[col * 40 + kk];
                b[nj][1] = *(const unsigned*)&Bs[col * 40 + kk + 8];
            }
#pragma unroll
            for (int mi = 0; mi < 2; mi++)
#pragma unroll
                for (int nj = 0; nj < 8; nj++)
                    mma16816(acc[mi][nj], a[mi], b[nj][0], b[nj][1]);
        }
        __syncthreads();
    }

#pragma unroll
    for (int mi = 0; mi < 2; mi++)
#pragma unroll
        for (int nj = 0; nj < 8; nj++)
#pragma unroll
            for (int e2 = 0; e2 < 2; e2++) {
                int row = bm + m0 + mi * 16 + g + e2 * 8;
                int col = bn + n0 + nj * 8 + 2 * t;
                float2 v;
                v.x = acc[mi][nj][e2 * 2 + 0] + bias[col];
                v.y = acc[mi][nj][e2 * 2 + 1] + bias[col + 1];
                *(float2*)&out[(size_t)row * 768 + col] = v;
            }
}

// ---------------------------------------------------------------------------
// rel_h table (fp32, validated)
// ---------------------------------------------------------------------------
__global__ __launch_bounds__(256) void relh_kernel(const float* __restrict__ rp) {
    __shared__ float Qs[64][64];
    __shared__ float Rs[64][64];
    const int qh = blockIdx.x, head = blockIdx.y;
    const int tid = threadIdx.x, tx = tid & 15, ty = tid >> 4;
    const size_t qbase = ((size_t)head * NQ + qh * 64) * HD;

    for (int idx = tid; idx < 4096; idx += 256) {
        int r = idx >> 6, c = idx & 63;
        Qs[r][c] = g_q[qbase + idx];
        Rs[r][c] = rp[(qh - r + 63) * 64 + c];
    }
    __syncthreads();

    float acc[4][4];
#pragma unroll
    for (int i = 0; i < 4; i++)
#pragma unroll
        for (int j = 0; j < 4; j++) acc[i][j] = 0.f;

    for (int c = 0; c < 64; c++) {
        float a[4], b[4];
#pragma unroll
        for (int i = 0; i < 4; i++) a[i] = Qs[ty * 4 + i][c];
#pragma unroll
        for (int j = 0; j < 4; j++) b[j] = Rs[tx * 4 + j][c];
#pragma unroll
        for (int i = 0; i < 4; i++)
#pragma unroll
            for (int j = 0; j < 4; j++) acc[i][j] = fmaf(a[i], b[j], acc[i][j]);
    }
#pragma unroll
    for (int i = 0; i < 4; i++)
#pragma unroll
        for (int j = 0; j < 4; j++)
            g_relh[qbase + (size_t)(ty * 4 + i) * 64 + (tx * 4 + j)] = acc[i][j];
}

// ---------------------------------------------------------------------------
// rel_w table (fp32, validated)
// ---------------------------------------------------------------------------
__global__ __launch_bounds__(256) void relw_kernel(const float* __restrict__ rp) {
    __shared__ float Qs[64][64];
    __shared__ float Rs[127][64];
    const int qh = blockIdx.x, head = blockIdx.y;
    const int tid = threadIdx.x, tx = tid & 15, ty = tid >> 4;
    const size_t qbase = ((size_t)head * NQ + qh * 64) * HD;

    for (int idx = tid; idx < 4096; idx += 256) {
        int r = idx >> 6, c = idx & 63;
        Qs[r][c] = g_q[qbase + idx];
    }
    for (int idx = tid; idx < 127 * 64; idx += 256) {
        Rs[idx >> 6][idx & 63] = rp[idx];
    }
    __syncthreads();

    float acc[4][4];
#pragma unroll
    for (int i = 0; i < 4; i++)
#pragma unroll
        for (int j = 0; j < 4; j++) acc[i][j] = 0.f;

    for (int c = 0; c < 64; c++) {
        float a[4];
#pragma unroll
        for (int i = 0; i < 4; i++) a[i] = Qs[ty * 4 + i][c];
#pragma unroll
        for (int i = 0; i < 4; i++) {
            int qw = ty * 4 + i;
#pragma unroll
            for (int j = 0; j < 4; j++) {
                int kw = tx * 4 + j;
                acc[i][j] = fmaf(a[i], Rs[qw - kw + 63][c], acc[i][j]);
            }
        }
    }
#pragma unroll
    for (int i = 0; i < 4; i++)
#pragma unroll
        for (int j = 0; j < 4; j++)
            g_relw[qbase + (size_t)(ty * 4 + i) * 64 + (tx * 4 + j)] = acc[i][j];
}

// ---------------------------------------------------------------------------
// Tensor-core flash attention (validated R3 body; fp16 output to g_ao16).
// ---------------------------------------------------------------------------
__global__ __launch_bounds__(128) void flash_attn() {
    extern __shared__ __half smd[];
    __half* Qs  = smd;                 // 4608
    __half* Ksh = smd + 4608;          // 2 x 4608
    __half* Vsh = smd + 13824;         // 2 x 4608
    __half* RWs = smd + 23040;         // 4608  [q][kw]
    __half* RHs = smd + 27648;         // 4608  [q][kh]

    const int qh = blockIdx.x, head = blockIdx.y;
    const int tid  = threadIdx.x;
    const int w    = tid >> 5;
    const int lane = tid & 31;
    const int g    = lane >> 2;
    const int t    = lane & 3;
    const int r0 = 16 * w + g;
    const int r1 = r0 + 8;

    const size_t qbase = ((size_t)head * NQ + qh * 64) * HD;
    const size_t hbase = (size_t)head * NQ * HD;

    {
        const unsigned* gq = (const unsigned*)(g_q16 + qbase);
        for (int i = tid; i < 2048; i += 128) {
            int r = i >> 5, c2 = i & 31;
            *(unsigned*)&Qs[r * 72 + c2 * 2] = gq[i];
        }
        for (int i = tid; i < 4096; i += 128) {
            int r = i >> 6, c = i & 63;
            RWs[r * 72 + c] = __float2half(g_relw[qbase + i]);
            RHs[r * 72 + c] = __float2half(g_relh[qbase + i]);
        }
    }

    {
        const __half* gk = g_k16 + hbase;
        const __half* gv = g_v16 + hbase;
#pragma unroll
        for (int i = 0; i < 4; i++) {
            int c = tid + i * 128;
            int key = c >> 3, off = (c & 7) * 8;
            cp_async16(&Ksh[key * 72 + off], gk + c * 8);
            cp_async16(&Vsh[key * 72 + off], gv + c * 8);
        }
        CP_COMMIT;
    }
    __syncthreads();

    unsigned qa[4][4];
#pragma unroll
    for (int u = 0; u < 4; u++) {
        int d = 16 * u + 2 * t;
        qa[u][0] = *(const unsigned*)&Qs[r0 * 72 + d];
        qa[u][1] = *(const unsigned*)&Qs[r1 * 72 + d];
        qa[u][2] = *(const unsigned*)&Qs[r0 * 72 + d + 8];
        qa[u][3] = *(const unsigned*)&Qs[r1 * 72 + d + 8];
    }

    float o[8][4];
#pragma unroll
    for (int j = 0; j < 8; j++)
#pragma unroll
        for (int e = 0; e < 4; e++) o[j][e] = 0.f;
    float m0 = -1e30f, m1 = -1e30f, l0 = 0.f, l1 = 0.f;

    for (int kt = 0; kt < 64; kt++) {
        const int cur = kt & 1;
        if (kt < 63) {
            const __half* gk = g_k16 + hbase + (size_t)(kt + 1) * 4096;
            const __half* gv = g_v16 + hbase + (size_t)(kt + 1) * 4096;
            __half* dk = Ksh + (cur ^ 1) * 4608;
            __half* dv = Vsh + (cur ^ 1) * 4608;
#pragma unroll
            for (int i = 0; i < 4; i++) {
                int c = tid + i * 128;
                int key = c >> 3, off = (c & 7) * 8;
                cp_async16(&dk[key * 72 + off], gk + c * 8);
                cp_async16(&dv[key * 72 + off], gv + c * 8);
            }
            CP_COMMIT;
            CP_WAIT(1);
        } else {
            CP_WAIT(0);
        }
        __syncthreads();

        const __half* K = Ksh + cur * 4608;
        const __half* V = Vsh + cur * 4608;

        float c[8][4];
#pragma unroll
        for (int j = 0; j < 8; j++)
#pragma unroll
            for (int e = 0; e < 4; e++) c[j][e] = 0.f;
#pragma unroll
        for (int u = 0; u < 4; u++) {
            int d = 16 * u + 2 * t;
#pragma unroll
            for (int j = 0; j < 8; j++) {
                int key = 8 * j + g;
                unsigned b0 = *(const unsigned*)&K[key * 72 + d];
                unsigned b1 = *(const unsigned*)&K[key * 72 + d + 8];
                mma16816(c[j], qa[u], b0, b1);
            }
        }

        float rh0 = __half2float(RHs[r0 * 72 + kt]);
        float rh1 = __half2float(RHs[r1 * 72 + kt]);
#pragma unroll
        for (int j = 0; j < 8; j++) {
            int col = 8 * j + 2 * t;
            float2 w0 = __half22float2(*(const __half2*)&RWs[r0 * 72 + col]);
            float2 w1 = __half22float2(*(const __half2*)&RWs[r1 * 72 + col]);
            c[j][0] += rh0 + w0.x;
            c[j][1] += rh0 + w0.y;
            c[j][2] += rh1 + w1.x;
            c[j][3] += rh1 + w1.y;
        }

        float mx0 = -1e30f, mx1 = -1e30f;
#pragma unroll
        for (int j = 0; j < 8; j++) {
            mx0 = fmaxf(mx0, fmaxf(c[j][0], c[j][1]));
            mx1 = fmaxf(mx1, fmaxf(c[j][2], c[j][3]));
        }
        mx0 = fmaxf(mx0, __shfl_xor_sync(0xffffffffu, mx0, 1));
        mx0 = fmaxf(mx0, __shfl_xor_sync(0xffffffffu, mx0, 2));
        mx1 = fmaxf(mx1, __shfl_xor_sync(0xffffffffu, mx1, 1));
        mx1 = fmaxf(mx1, __shfl_xor_sync(0xffffffffu, mx1, 2));

        float mn0 = fmaxf(m0, mx0), mn1 = fmaxf(m1, mx1);
        float al0 = __expf(m0 - mn0), al1 = __expf(m1 - mn1);
        m0 = mn0; m1 = mn1;

        float s0 = 0.f, s1 = 0.f;
#pragma unroll
        for (int j = 0; j < 8; j++) {
            c[j][0] = __expf(c[j][0] - mn0); s0 += c[j][0];
            c[j][1] = __expf(c[j][1] - mn0); s0 += c[j][1];
            c[j][2] = __expf(c[j][2] - mn1); s1 += c[j][2];
            c[j][3] = __expf(c[j][3] - mn1); s1 += c[j][3];
        }
        s0 += __shfl_xor_sync(0xffffffffu, s0, 1);
        s0 += __shfl_xor_sync(0xffffffffu, s0, 2);
        s1 += __shfl_xor_sync(0xffffffffu, s1, 1);
        s1 += __shfl_xor_sync(0xffffffffu, s1, 2);
        l0 = l0 * al0 + s0;
        l1 = l1 * al1 + s1;

#pragma unroll
        for (int j = 0; j < 8; j++) {
            o[j][0] *= al0; o[j][1] *= al0;
            o[j][2] *= al1; o[j][3] *= al1;
        }

        const unsigned short* Vu = (const unsigned short*)V;
#pragma unroll
        for (int u = 0; u < 4; u++) {
            unsigned pa[4];
            pa[0] = f2h2(c[2 * u][0], c[2 * u][1]);
            pa[1] = f2h2(c[2 * u][2], c[2 * u][3]);
            pa[2] = f2h2(c[2 * u + 1][0], c[2 * u + 1][1]);
            pa[3] = f2h2(c[2 * u + 1][2], c[2 * u + 1][3]);
            int kr = 16 * u + 2 * t;
#pragma unroll
            for (int j = 0; j < 8; j++) {
                int col = 8 * j + g;
                unsigned v0 = Vu[(kr)     * 72 + col];
                unsigned v1 = Vu[(kr + 1) * 72 + col];
                unsigned v2 = Vu[(kr + 8) * 72 + col];
                unsigned v3 = Vu[(kr + 9) * 72 + col];
                mma16816(o[j], pa, v0 | (v1 << 16), v2 | (v3 << 16));
            }
        }
        __syncthreads();
    }

    float inv0 = 1.f / l0, inv1 = 1.f / l1;
    __half* outp = g_ao16 + (size_t)(qh * 64) * CDIM + head * 64;
#pragma unroll
    for (int j = 0; j < 8; j++) {
        int col = 8 * j + 2 * t;
        *(__half2*)&outp[(size_t)r0 * CDIM + col] =
            __floats2half2_rn(o[j][0] * inv0, o[j][1] * inv0);
        *(__half2*)&outp[(size_t)r1 * CDIM + col] =
            __floats2half2_rn(o[j][2] * inv1, o[j][3] * inv1);
    }
}

// ---------------------------------------------------------------------------
extern "C" void kernel_launch(void* const* d_in, const int* in_sizes, int n_in,
                              void* d_out, int out_size) {
    const float* x      = (const float*)d_in[0];
    const float* qkv_w  = (const float*)d_in[1];
    const float* qkv_b  = (const float*)d_in[2];
    const float* proj_w = (const float*)d_in[3];
    const float* proj_b = (const float*)d_in[4];
    const float* rph    = (const float*)d_in[5];
    const float* rpw    = (const float*)d_in[6];
    float* out = (float*)d_out;

    const int GEMM_SMEM  = 10240 * 2;   // 20480 B
    const int FLASH_SMEM = 32256 * 2;   // 64512 B
    cudaFuncSetAttribute(flash_attn, cudaFuncAttributeMaxDynamicSharedMemorySize, FLASH_SMEM);

    qkv_hgemm<<<dim3(18, 32), 256, GEMM_SMEM>>>(x, qkv_w, qkv_b);
    relh_kernel<<<dim3(64, 12), 256>>>(rph);
    relw_kernel<<<dim3(64, 12), 256>>>(rpw);
    flash_attn<<<dim3(64, 12), 128, FLASH_SMEM>>>();
    proj_hgemm<<<dim3(6, 32), 256, GEMM_SMEM>>>(proj_w, proj_b, out);
}

// round 7
// speedup vs baseline: 4.0597x; 1.3750x over previous
#include <cuda_runtime.h>
#include <cuda_fp16.h>

// SAM Vision Attention: B=1, H=W=64, N=4096, C=768, nh=12, hd=64
// R7: R6 with the launch bug fixed — transpose kernels reference the
//     __device__ fp16 weight arrays from device code instead of taking
//     them as host-passed arguments (host-side __device__ symbol = UB).

#define NH 12
#define NQ 4096
#define HD 64
#define CDIM 768
#define SCALE 0.125f   // 64^-0.5, exact in fp16

__device__ float  g_q[NH * NQ * HD];          // fp32 q for rel tables
__device__ __half g_q16[NH * NQ * HD];
__device__ __half g_k16[NH * NQ * HD];        // pre-scaled by SCALE
__device__ __half g_v16[NH * NQ * HD];
__device__ float  g_relh[NH * NQ * HD];
__device__ float  g_relw[NH * NQ * HD];
__device__ __half g_ao16[NQ * CDIM];          // attention output (proj A input)
__device__ __half g_x16[NQ * CDIM];           // x in fp16
__device__ __half g_wqkvT[3 * CDIM * CDIM];   // qkv_w^T  [2304][768] fp16
__device__ __half g_wprojT[CDIM * CDIM];      // proj_w^T [768][768] fp16

// ---------------------------------------------------------------------------
// helpers
// ---------------------------------------------------------------------------
__device__ __forceinline__ void mma16816(float* c, const unsigned* a,
                                         unsigned b0, unsigned b1) {
    asm volatile(
        "mma.sync.aligned.m16n8k16.row.col.f32.f16.f16.f32 "
        "{%0,%1,%2,%3}, {%4,%5,%6,%7}, {%8,%9}, {%0,%1,%2,%3};\n"
        : "+f"(c[0]), "+f"(c[1]), "+f"(c[2]), "+f"(c[3])
        : "r"(a[0]), "r"(a[1]), "r"(a[2]), "r"(a[3]), "r"(b0), "r"(b1));
}

__device__ __forceinline__ unsigned f2h2(float x, float y) {
    __half2 h = __floats2half2_rn(x, y);
    return *(unsigned*)&h;
}

__device__ __forceinline__ void cp_async16(void* dst, const void* src) {
    unsigned d = (unsigned)__cvta_generic_to_shared(dst);
    asm volatile("cp.async.cg.shared.global [%0], [%1], 16;\n" :: "r"(d), "l"(src));
}
#define CP_COMMIT asm volatile("cp.async.commit_group;\n")
#define CP_WAIT(n) asm volatile("cp.async.wait_group %0;\n" :: "n"(n))

__device__ __forceinline__ void ldsm4(unsigned& r0, unsigned& r1, unsigned& r2,
                                      unsigned& r3, unsigned a) {
    asm volatile("ldmatrix.sync.aligned.m8n8.x4.shared.b16 {%0,%1,%2,%3}, [%4];"
                 : "=r"(r0), "=r"(r1), "=r"(r2), "=r"(r3) : "r"(a));
}
__device__ __forceinline__ void ldsm4t(unsigned& r0, unsigned& r1, unsigned& r2,
                                       unsigned& r3, unsigned a) {
    asm volatile("ldmatrix.sync.aligned.m8n8.x4.trans.shared.b16 {%0,%1,%2,%3}, [%4];"
                 : "=r"(r0), "=r"(r1), "=r"(r2), "=r"(r3) : "r"(a));
}

// ---------------------------------------------------------------------------
// one-time conversion kernels (globals referenced from device code only)
// ---------------------------------------------------------------------------
__global__ void conv_x_kernel(const float* __restrict__ X) {
    int i = blockIdx.x * 256 + threadIdx.x;     // one float4 -> 4 halves
    if (i < NQ * CDIM / 4) {
        float4 v = ((const float4*)X)[i];
        __half2* o = (__half2*)(g_x16 + i * 4);
        o[0] = __floats2half2_rn(v.x, v.y);
        o[1] = __floats2half2_rn(v.z, v.w);
    }
}

// qkv_w [768][2304] fp32 -> g_wqkvT [2304][768] fp16
__global__ void transpose_qkv_kernel(const float* __restrict__ W) {
    __shared__ float tile[32][33];
    int bn = blockIdx.x * 32, bk = blockIdx.y * 32;
    int tx = threadIdx.x, ty = threadIdx.y;     // 32 x 8
#pragma unroll
    for (int i = 0; i < 32; i += 8)
        tile[ty + i][tx] = W[(size_t)(bk + ty + i) * 2304 + bn + tx];
    __syncthreads();
#pragma unroll
    for (int i = 0; i < 32; i += 8)
        g_wqkvT[(size_t)(bn + ty + i) * 768 + bk + tx] = __float2half(tile[tx][ty + i]);
}

// proj_w [768][768] fp32 -> g_wprojT [768][768] fp16
__global__ void transpose_proj_kernel(const float* __restrict__ W) {
    __shared__ float tile[32][33];
    int bn = blockIdx.x * 32, bk = blockIdx.y * 32;
    int tx = threadIdx.x, ty = threadIdx.y;
#pragma unroll
    for (int i = 0; i < 32; i += 8)
        tile[ty + i][tx] = W[(size_t)(bk + ty + i) * 768 + bn + tx];
    __syncthreads();
#pragma unroll
    for (int i = 0; i < 32; i += 8)
        g_wprojT[(size_t)(bn + ty + i) * 768 + bk + tx] = __float2half(tile[tx][ty + i]);
}

// ---------------------------------------------------------------------------
// QKV GEMM (fp16 HMMA, cp.async double-buffered): M=4096, N=2304, K=768.
// A = g_x16 [M][768], B = g_wqkvT [N][768] (both k-contiguous fp16).
// smem (dynamic, halves): As[2][128*40] at 0 | Bs[2][128*40] at 10240.
// ---------------------------------------------------------------------------
__global__ __launch_bounds__(256) void qkv_hgemm16(const float* __restrict__ bias) {
    extern __shared__ __half smq[];
    __half* As = smq;
    __half* Bs = smq + 10240;

    const int bm = blockIdx.y * 128, bn = blockIdx.x * 128;
    const int tid = threadIdx.x;
    const int w = tid >> 5, lane = tid & 31;
    const int g = lane >> 2, t = lane & 3;
    const int m0 = (w >> 1) * 32, n0 = (w & 1) * 64;

    float acc[2][8][4];
#pragma unroll
    for (int mi = 0; mi < 2; mi++)
#pragma unroll
        for (int nj = 0; nj < 8; nj++)
#pragma unroll
            for (int e = 0; e < 4; e++) acc[mi][nj][e] = 0.f;

#pragma unroll
    for (int i = 0; i < 2; i++) {
        int cdx = tid + i * 256;                 // 0..511
        int row = cdx >> 2, off = (cdx & 3) * 8;
        cp_async16(As + row * 40 + off, g_x16 + (size_t)(bm + row) * 768 + off);
        cp_async16(Bs + row * 40 + off, g_wqkvT + (size_t)(bn + row) * 768 + off);
    }
    CP_COMMIT;

    for (int kt = 0; kt < 24; kt++) {
        const int cur = kt & 1;
        if (kt < 23) {
            int k0 = (kt + 1) * 32;
            __half* dA = As + (cur ^ 1) * 5120;
            __half* dB = Bs + (cur ^ 1) * 5120;
#pragma unroll
            for (int i = 0; i < 2; i++) {
                int cdx = tid + i * 256;
                int row = cdx >> 2, off = (cdx & 3) * 8;
                cp_async16(dA + row * 40 + off, g_x16 + (size_t)(bm + row) * 768 + k0 + off);
                cp_async16(dB + row * 40 + off, g_wqkvT + (size_t)(bn + row) * 768 + k0 + off);
            }
            CP_COMMIT;
            CP_WAIT(1);
        } else {
            CP_WAIT(0);
        }
        __syncthreads();

        const __half* Ab = As + cur * 5120;
        const __half* Bb = Bs + cur * 5120;
#pragma unroll
        for (int ks = 0; ks < 2; ks++) {
            unsigned a[2][4], b[8][2];
#pragma unroll
            for (int mi = 0; mi < 2; mi++) {
                int row = m0 + mi * 16 + g;
                int kk = ks * 16 + 2 * t;
                a[mi][0] = *(const unsigned*)&Ab[row * 40 + kk];
                a[mi][1] = *(const unsigned*)&Ab[(row + 8) * 40 + kk];
                a[mi][2] = *(const unsigned*)&Ab[row * 40 + kk + 8];
                a[mi][3] = *(const unsigned*)&Ab[(row + 8) * 40 + kk + 8];
            }
#pragma unroll
            for (int nj = 0; nj < 8; nj++) {
                int col = n0 + nj * 8 + g;
                int kk = ks * 16 + 2 * t;
                b[nj][0] = *(const unsigned*)&Bb[col * 40 + kk];
                b[nj][1] = *(const unsigned*)&Bb[col * 40 + kk + 8];
            }
#pragma unroll
            for (int mi = 0; mi < 2; mi++)
#pragma unroll
                for (int nj = 0; nj < 8; nj++)
                    mma16816(acc[mi][nj], a[mi], b[nj][0], b[nj][1]);
        }
        __syncthreads();
    }

#pragma unroll
    for (int mi = 0; mi < 2; mi++)
#pragma unroll
        for (int nj = 0; nj < 8; nj++)
#pragma unroll
            for (int e = 0; e < 4; e++) {
                int row = bm + m0 + mi * 16 + g + (e >> 1) * 8;
                int col = bn + n0 + nj * 8 + 2 * t + (e & 1);
                float val = acc[mi][nj][e] + bias[col];
                int which = col / 768;
                int rem = col - which * 768;
                int head = rem >> 6, d = rem & 63;
                size_t off = ((size_t)head * NQ + row) * HD + d;
                if (which == 0) { g_q[off] = val; g_q16[off] = __float2half(val); }
                else if (which == 1) g_k16[off] = __float2half(val * SCALE);
                else g_v16[off] = __float2half(val);
            }
}

// ---------------------------------------------------------------------------
// proj GEMM (fp16 HMMA, cp.async double-buffered): M=4096, N=768.
// ---------------------------------------------------------------------------
__global__ __launch_bounds__(256) void proj_hgemm16(const float* __restrict__ bias,
                                                    float* __restrict__ out) {
    extern __shared__ __half smp[];
    __half* As = smp;
    __half* Bs = smp + 10240;

    const int bm = blockIdx.y * 128, bn = blockIdx.x * 128;
    const int tid = threadIdx.x;
    const int w = tid >> 5, lane = tid & 31;
    const int g = lane >> 2, t = lane & 3;
    const int m0 = (w >> 1) * 32, n0 = (w & 1) * 64;

    float acc[2][8][4];
#pragma unroll
    for (int mi = 0; mi < 2; mi++)
#pragma unroll
        for (int nj = 0; nj < 8; nj++)
#pragma unroll
            for (int e = 0; e < 4; e++) acc[mi][nj][e] = 0.f;

#pragma unroll
    for (int i = 0; i < 2; i++) {
        int cdx = tid + i * 256;
        int row = cdx >> 2, off = (cdx & 3) * 8;
        cp_async16(As + row * 40 + off, g_ao16 + (size_t)(bm + row) * 768 + off);
        cp_async16(Bs + row * 40 + off, g_wprojT + (size_t)(bn + row) * 768 + off);
    }
    CP_COMMIT;

    for (int kt = 0; kt < 24; kt++) {
        const int cur = kt & 1;
        if (kt < 23) {
            int k0 = (kt + 1) * 32;
            __half* dA = As + (cur ^ 1) * 5120;
            __half* dB = Bs + (cur ^ 1) * 5120;
#pragma unroll
            for (int i = 0; i < 2; i++) {
                int cdx = tid + i * 256;
                int row = cdx >> 2, off = (cdx & 3) * 8;
                cp_async16(dA + row * 40 + off, g_ao16 + (size_t)(bm + row) * 768 + k0 + off);
                cp_async16(dB + row * 40 + off, g_wprojT + (size_t)(bn + row) * 768 + k0 + off);
            }
            CP_COMMIT;
            CP_WAIT(1);
        } else {
            CP_WAIT(0);
        }
        __syncthreads();

        const __half* Ab = As + cur * 5120;
        const __half* Bb = Bs + cur * 5120;
#pragma unroll
        for (int ks = 0; ks < 2; ks++) {
            unsigned a[2][4], b[8][2];
#pragma unroll
            for (int mi = 0; mi < 2; mi++) {
                int row = m0 + mi * 16 + g;
                int kk = ks * 16 + 2 * t;
                a[mi][0] = *(const unsigned*)&Ab[row * 40 + kk];
                a[mi][1] = *(const unsigned*)&Ab[(row + 8) * 40 + kk];
                a[mi][2] = *(const unsigned*)&Ab[row * 40 + kk + 8];
                a[mi][3] = *(const unsigned*)&Ab[(row + 8) * 40 + kk + 8];
            }
#pragma unroll
            for (int nj = 0; nj < 8; nj++) {
                int col = n0 + nj * 8 + g;
                int kk = ks * 16 + 2 * t;
                b[nj][0] = *(const unsigned*)&Bb[col * 40 + kk];
                b[nj][1] = *(const unsigned*)&Bb[col * 40 + kk + 8];
            }
#pragma unroll
            for (int mi = 0; mi < 2; mi++)
#pragma unroll
                for (int nj = 0; nj < 8; nj++)
                    mma16816(acc[mi][nj], a[mi], b[nj][0], b[nj][1]);
        }
        __syncthreads();
    }

#pragma unroll
    for (int mi = 0; mi < 2; mi++)
#pragma unroll
        for (int nj = 0; nj < 8; nj++)
#pragma unroll
            for (int e2 = 0; e2 < 2; e2++) {
                int row = bm + m0 + mi * 16 + g + e2 * 8;
                int col = bn + n0 + nj * 8 + 2 * t;
                float2 v;
                v.x = acc[mi][nj][e2 * 2 + 0] + bias[col];
                v.y = acc[mi][nj][e2 * 2 + 1] + bias[col + 1];
                *(float2*)&out[(size_t)row * 768 + col] = v;
            }
}

// ---------------------------------------------------------------------------
// rel_h table (fp32, validated)
// ---------------------------------------------------------------------------
__global__ __launch_bounds__(256) void relh_kernel(const float* __restrict__ rp) {
    __shared__ float Qs[64][64];
    __shared__ float Rs[64][64];
    const int qh = blockIdx.x, head = blockIdx.y;
    const int tid = threadIdx.x, tx = tid & 15, ty = tid >> 4;
    const size_t qbase = ((size_t)head * NQ + qh * 64) * HD;

    for (int idx = tid; idx < 4096; idx += 256) {
        int r = idx >> 6, c = idx & 63;
        Qs[r][c] = g_q[qbase + idx];
        Rs[r][c] = rp[(qh - r + 63) * 64 + c];
    }
    __syncthreads();

    float acc[4][4];
#pragma unroll
    for (int i = 0; i < 4; i++)
#pragma unroll
        for (int j = 0; j < 4; j++) acc[i][j] = 0.f;

    for (int c = 0; c < 64; c++) {
        float a[4], b[4];
#pragma unroll
        for (int i = 0; i < 4; i++) a[i] = Qs[ty * 4 + i][c];
#pragma unroll
        for (int j = 0; j < 4; j++) b[j] = Rs[tx * 4 + j][c];
#pragma unroll
        for (int i = 0; i < 4; i++)
#pragma unroll
            for (int j = 0; j < 4; j++) acc[i][j] = fmaf(a[i], b[j], acc[i][j]);
    }
#pragma unroll
    for (int i = 0; i < 4; i++)
#pragma unroll
        for (int j = 0; j < 4; j++)
            g_relh[qbase + (size_t)(ty * 4 + i) * 64 + (tx * 4 + j)] = acc[i][j];
}

// ---------------------------------------------------------------------------
// rel_w table (fp32, validated)
// ---------------------------------------------------------------------------
__global__ __launch_bounds__(256) void relw_kernel(const float* __restrict__ rp) {
    __shared__ float Qs[64][64];
    __shared__ float Rs[127][64];
    const int qh = blockIdx.x, head = blockIdx.y;
    const int tid = threadIdx.x, tx = tid & 15, ty = tid >> 4;
    const size_t qbase = ((size_t)head * NQ + qh * 64) * HD;

    for (int idx = tid; idx < 4096; idx += 256) {
        int r = idx >> 6, c = idx & 63;
        Qs[r][c] = g_q[qbase + idx];
    }
    for (int idx = tid; idx < 127 * 64; idx += 256) {
        Rs[idx >> 6][idx & 63] = rp[idx];
    }
    __syncthreads();

    float acc[4][4];
#pragma unroll
    for (int i = 0; i < 4; i++)
#pragma unroll
        for (int j = 0; j < 4; j++) acc[i][j] = 0.f;

    for (int c = 0; c < 64; c++) {
        float a[4];
#pragma unroll
        for (int i = 0; i < 4; i++) a[i] = Qs[ty * 4 + i][c];
#pragma unroll
        for (int i = 0; i < 4; i++) {
            int qw = ty * 4 + i;
#pragma unroll
            for (int j = 0; j < 4; j++) {
                int kw = tx * 4 + j;
                acc[i][j] = fmaf(a[i], Rs[qw - kw + 63][c], acc[i][j]);
            }
        }
    }
#pragma unroll
    for (int i = 0; i < 4; i++)
#pragma unroll
        for (int j = 0; j < 4; j++)
            g_relw[qbase + (size_t)(ty * 4 + i) * 64 + (tx * 4 + j)] = acc[i][j];
}

// ---------------------------------------------------------------------------
// Tensor-core flash attention with ldmatrix fragment loads
// (output-identical to validated R5 per R4/R6 rel_err equality).
// ---------------------------------------------------------------------------
__global__ __launch_bounds__(128) void flash_attn() {
    extern __shared__ __half smd[];
    __half* Qs  = smd;                 // 4608
    __half* Ksh = smd + 4608;          // 2 x 4608
    __half* Vsh = smd + 13824;         // 2 x 4608
    __half* RWs = smd + 23040;         // 4608  [q][kw]
    __half* RHs = smd + 27648;         // 4608  [q][kh]

    const int qh = blockIdx.x, head = blockIdx.y;
    const int tid  = threadIdx.x;
    const int w    = tid >> 5;
    const int lane = tid & 31;
    const int g    = lane >> 2;
    const int t    = lane & 3;
    const int r0 = 16 * w + g;
    const int r1 = r0 + 8;

    const size_t qbase = ((size_t)head * NQ + qh * 64) * HD;
    const size_t hbase = (size_t)head * NQ * HD;

    const int mat = lane >> 3, mr = lane & 7;
    const unsigned kbase0 = (unsigned)__cvta_generic_to_shared(Ksh);
    const unsigned vbase0 = (unsigned)__cvta_generic_to_shared(Vsh);
    const unsigned kconst = ((mat >> 1) * 8 + mr) * 144 + (mat & 1) * 16;
    const unsigned vconst = ((mat & 1) * 8 + mr) * 144 + (mat >> 1) * 16;

    {
        const unsigned* gq = (const unsigned*)(g_q16 + qbase);
        for (int i = tid; i < 2048; i += 128) {
            int r = i >> 5, c2 = i & 31;
            *(unsigned*)&Qs[r * 72 + c2 * 2] = gq[i];
        }
        for (int i = tid; i < 4096; i += 128) {
            int r = i >> 6, c = i & 63;
            RWs[r * 72 + c] = __float2half(g_relw[qbase + i]);
            RHs[r * 72 + c] = __float2half(g_relh[qbase + i]);
        }
    }

    {
        const __half* gk = g_k16 + hbase;
        const __half* gv = g_v16 + hbase;
#pragma unroll
        for (int i = 0; i < 4; i++) {
            int c = tid + i * 128;
            int key = c >> 3, off = (c & 7) * 8;
            cp_async16(&Ksh[key * 72 + off], gk + c * 8);
            cp_async16(&Vsh[key * 72 + off], gv + c * 8);
        }
        CP_COMMIT;
    }
    __syncthreads();

    unsigned qa[4][4];
#pragma unroll
    for (int u = 0; u < 4; u++) {
        int d = 16 * u + 2 * t;
        qa[u][0] = *(const unsigned*)&Qs[r0 * 72 + d];
        qa[u][1] = *(const unsigned*)&Qs[r1 * 72 + d];
        qa[u][2] = *(const unsigned*)&Qs[r0 * 72 + d + 8];
        qa[u][3] = *(const unsigned*)&Qs[r1 * 72 + d + 8];
    }

    float o[8][4];
#pragma unroll
    for (int j = 0; j < 8; j++)
#pragma unroll
        for (int e = 0; e < 4; e++) o[j][e] = 0.f;
    float m0 = -1e30f, m1 = -1e30f, l0 = 0.f, l1 = 0.f;

    for (int kt = 0; kt < 64; kt++) {
        const int cur = kt & 1;
        if (kt < 63) {
            const __half* gk = g_k16 + hbase + (size_t)(kt + 1) * 4096;
            const __half* gv = g_v16 + hbase + (size_t)(kt + 1) * 4096;
            __half* dk = Ksh + (cur ^ 1) * 4608;
            __half* dv = Vsh + (cur ^ 1) * 4608;
#pragma unroll
            for (int i = 0; i < 4; i++) {
                int c = tid + i * 128;
                int key = c >> 3, off = (c & 7) * 8;
                cp_async16(&dk[key * 72 + off], gk + c * 8);
                cp_async16(&dv[key * 72 + off], gv + c * 8);
            }
            CP_COMMIT;
            CP_WAIT(1);
        } else {
            CP_WAIT(0);
        }
        __syncthreads();

        float c[8][4];
#pragma unroll
        for (int j = 0; j < 8; j++)
#pragma unroll
            for (int e = 0; e < 4; e++) c[j][e] = 0.f;
        {
            const unsigned kb = kbase0 + cur * 9216 + kconst;
#pragma unroll
            for (int u = 0; u < 4; u++) {
#pragma unroll
                for (int j2 = 0; j2 < 4; j2++) {
                    unsigned b0, b1, b2, b3;
                    ldsm4(b0, b1, b2, b3, kb + j2 * 2304 + u * 32);
                    mma16816(c[2 * j2],     qa[u], b0, b1);
                    mma16816(c[2 * j2 + 1], qa[u], b2, b3);
                }
            }
        }

        float rh0 = __half2float(RHs[r0 * 72 + kt]);
        float rh1 = __half2float(RHs[r1 * 72 + kt]);
#pragma unroll
        for (int j = 0; j < 8; j++) {
            int col = 8 * j + 2 * t;
            float2 w0 = __half22float2(*(const __half2*)&RWs[r0 * 72 + col]);
            float2 w1 = __half22float2(*(const __half2*)&RWs[r1 * 72 + col]);
            c[j][0] += rh0 + w0.x;
            c[j][1] += rh0 + w0.y;
            c[j][2] += rh1 + w1.x;
            c[j][3] += rh1 + w1.y;
        }

        float mx0 = -1e30f, mx1 = -1e30f;
#pragma unroll
        for (int j = 0; j < 8; j++) {
            mx0 = fmaxf(mx0, fmaxf(c[j][0], c[j][1]));
            mx1 = fmaxf(mx1, fmaxf(c[j][2], c[j][3]));
        }
        mx0 = fmaxf(mx0, __shfl_xor_sync(0xffffffffu, mx0, 1));
        mx0 = fmaxf(mx0, __shfl_xor_sync(0xffffffffu, mx0, 2));
        mx1 = fmaxf(mx1, __shfl_xor_sync(0xffffffffu, mx1, 1));
        mx1 = fmaxf(mx1, __shfl_xor_sync(0xffffffffu, mx1, 2));

        float mn0 = fmaxf(m0, mx0), mn1 = fmaxf(m1, mx1);
        float al0 = __expf(m0 - mn0), al1 = __expf(m1 - mn1);
        m0 = mn0; m1 = mn1;

        float s0 = 0.f, s1 = 0.f;
#pragma unroll
        for (int j = 0; j < 8; j++) {
            c[j][0] = __expf(c[j][0] - mn0); s0 += c[j][0];
            c[j][1] = __expf(c[j][1] - mn0); s0 += c[j][1];
            c[j][2] = __expf(c[j][2] - mn1); s1 += c[j][2];
            c[j][3] = __expf(c[j][3] - mn1); s1 += c[j][3];
        }
        s0 += __shfl_xor_sync(0xffffffffu, s0, 1);
        s0 += __shfl_xor_sync(0xffffffffu, s0, 2);
        s1 += __shfl_xor_sync(0xffffffffu, s1, 1);
        s1 += __shfl_xor_sync(0xffffffffu, s1, 2);
        l0 = l0 * al0 + s0;
        l1 = l1 * al1 + s1;

#pragma unroll
        for (int j = 0; j < 8; j++) {
            o[j][0] *= al0; o[j][1] *= al0;
            o[j][2] *= al1; o[j][3] *= al1;
        }

        {
            const unsigned vb = vbase0 + cur * 9216 + vconst;
#pragma unroll
            for (int u = 0; u < 4; u++) {
                unsigned pa[4];
                pa[0] = f2h2(c[2 * u][0], c[2 * u][1]);
                pa[1] = f2h2(c[2 * u][2], c[2 * u][3]);
                pa[2] = f2h2(c[2 * u + 1][0], c[2 * u + 1][1]);
                pa[3] = f2h2(c[2 * u + 1][2], c[2 * u + 1][3]);
#pragma unroll
                for (int j2 = 0; j2 < 4; j2++) {
                    unsigned b0, b1, b2, b3;
                    ldsm4t(b0, b1, b2, b3, vb + u * 2304 + j2 * 32);
                    mma16816(o[2 * j2],     pa, b0, b1);
                    mma16816(o[2 * j2 + 1], pa, b2, b3);
                }
            }
        }
        __syncthreads();
    }

    float inv0 = 1.f / l0, inv1 = 1.f / l1;
    __half* outp = g_ao16 + (size_t)(qh * 64) * CDIM + head * 64;
#pragma unroll
    for (int j = 0; j < 8; j++) {
        int col = 8 * j + 2 * t;
        *(__half2*)&outp[(size_t)r0 * CDIM + col] =
            __floats2half2_rn(o[j][0] * inv0, o[j][1] * inv0);
        *(__half2*)&outp[(size_t)r1 * CDIM + col] =
            __floats2half2_rn(o[j][2] * inv1, o[j][3] * inv1);
    }
}

// ---------------------------------------------------------------------------
extern "C" void kernel_launch(void* const* d_in, const int* in_sizes, int n_in,
                              void* d_out, int out_size) {
    const float* x      = (const float*)d_in[0];
    const float* qkv_w  = (const float*)d_in[1];
    const float* qkv_b  = (const float*)d_in[2];
    const float* proj_w = (const float*)d_in[3];
    const float* proj_b = (const float*)d_in[4];
    const float* rph    = (const float*)d_in[5];
    const float* rpw    = (const float*)d_in[6];
    float* out = (float*)d_out;

    const int GEMM_SMEM  = 20480 * 2;   // 40960 B
    const int FLASH_SMEM = 32256 * 2;   // 64512 B
    cudaFuncSetAttribute(flash_attn, cudaFuncAttributeMaxDynamicSharedMemorySize, FLASH_SMEM);

    conv_x_kernel<<<(NQ * CDIM / 4 + 255) / 256, 256>>>(x);
    transpose_qkv_kernel<<<dim3(72, 24), dim3(32, 8)>>>(qkv_w);
    transpose_proj_kernel<<<dim3(24, 24), dim3(32, 8)>>>(proj_w);
    qkv_hgemm16<<<dim3(18, 32), 256, GEMM_SMEM>>>(qkv_b);
    relh_kernel<<<dim3(64, 12), 256>>>(rph);
    relw_kernel<<<dim3(64, 12), 256>>>(rpw);
    flash_attn<<<dim3(64, 12), 128, FLASH_SMEM>>>();
    proj_hgemm16<<<dim3(6, 32), 256, GEMM_SMEM>>>(proj_b, out);
}

// round 8
// speedup vs baseline: 6.6702x; 1.6430x over previous
#include <cuda_runtime.h>
#include <cuda_fp16.h>

// SAM Vision Attention: B=1, H=W=64, N=4096, C=768, nh=12, hd=64
// R8: rel-pos bias tables fused into flash_attn prologue via HMMA
//     (relh/relw kernels and fp32 g_q eliminated); exp2-based softmax
//     with log2e folded into k-scale and bias tables.

#define NH 12
#define NQ 4096
#define HD 64
#define CDIM 768
#define L2E 1.44269504f
#define SCALE_L2E (0.125f * 1.44269504f)   // 64^-0.5 * log2(e), folded into k

__device__ __half g_q16[NH * NQ * HD];
__device__ __half g_k16[NH * NQ * HD];        // pre-scaled by SCALE_L2E
__device__ __half g_v16[NH * NQ * HD];
__device__ __half g_ao16[NQ * CDIM];          // attention output (proj A input)
__device__ __half g_x16[NQ * CDIM];           // x in fp16
__device__ __half g_wqkvT[3 * CDIM * CDIM];   // qkv_w^T  [2304][768] fp16
__device__ __half g_wprojT[CDIM * CDIM];      // proj_w^T [768][768] fp16

// ---------------------------------------------------------------------------
// helpers
// ---------------------------------------------------------------------------
__device__ __forceinline__ void mma16816(float* c, const unsigned* a,
                                         unsigned b0, unsigned b1) {
    asm volatile(
        "mma.sync.aligned.m16n8k16.row.col.f32.f16.f16.f32 "
        "{%0,%1,%2,%3}, {%4,%5,%6,%7}, {%8,%9}, {%0,%1,%2,%3};\n"
        : "+f"(c[0]), "+f"(c[1]), "+f"(c[2]), "+f"(c[3])
        : "r"(a[0]), "r"(a[1]), "r"(a[2]), "r"(a[3]), "r"(b0), "r"(b1));
}

__device__ __forceinline__ unsigned f2h2(float x, float y) {
    __half2 h = __floats2half2_rn(x, y);
    return *(unsigned*)&h;
}

__device__ __forceinline__ float ex2f(float x) {
    float y;
    asm("ex2.approx.f32 %0, %1;" : "=f"(y) : "f"(x));
    return y;
}

__device__ __forceinline__ void cp_async16(void* dst, const void* src) {
    unsigned d = (unsigned)__cvta_generic_to_shared(dst);
    asm volatile("cp.async.cg.shared.global [%0], [%1], 16;\n" :: "r"(d), "l"(src));
}
#define CP_COMMIT asm volatile("cp.async.commit_group;\n")
#define CP_WAIT(n) asm volatile("cp.async.wait_group %0;\n" :: "n"(n))

__device__ __forceinline__ void ldsm4(unsigned& r0, unsigned& r1, unsigned& r2,
                                      unsigned& r3, unsigned a) {
    asm volatile("ldmatrix.sync.aligned.m8n8.x4.shared.b16 {%0,%1,%2,%3}, [%4];"
                 : "=r"(r0), "=r"(r1), "=r"(r2), "=r"(r3) : "r"(a));
}
__device__ __forceinline__ void ldsm4t(unsigned& r0, unsigned& r1, unsigned& r2,
                                       unsigned& r3, unsigned a) {
    asm volatile("ldmatrix.sync.aligned.m8n8.x4.trans.shared.b16 {%0,%1,%2,%3}, [%4];"
                 : "=r"(r0), "=r"(r1), "=r"(r2), "=r"(r3) : "r"(a));
}

// ---------------------------------------------------------------------------
// one-time conversion kernels (globals referenced from device code only)
// ---------------------------------------------------------------------------
__global__ void conv_x_kernel(const float* __restrict__ X) {
    int i = blockIdx.x * 256 + threadIdx.x;
    if (i < NQ * CDIM / 4) {
        float4 v = ((const float4*)X)[i];
        __half2* o = (__half2*)(g_x16 + i * 4);
        o[0] = __floats2half2_rn(v.x, v.y);
        o[1] = __floats2half2_rn(v.z, v.w);
    }
}

__global__ void transpose_qkv_kernel(const float* __restrict__ W) {
    __shared__ float tile[32][33];
    int bn = blockIdx.x * 32, bk = blockIdx.y * 32;
    int tx = threadIdx.x, ty = threadIdx.y;
#pragma unroll
    for (int i = 0; i < 32; i += 8)
        tile[ty + i][tx] = W[(size_t)(bk + ty + i) * 2304 + bn + tx];
    __syncthreads();
#pragma unroll
    for (int i = 0; i < 32; i += 8)
        g_wqkvT[(size_t)(bn + ty + i) * 768 + bk + tx] = __float2half(tile[tx][ty + i]);
}

__global__ void transpose_proj_kernel(const float* __restrict__ W) {
    __shared__ float tile[32][33];
    int bn = blockIdx.x * 32, bk = blockIdx.y * 32;
    int tx = threadIdx.x, ty = threadIdx.y;
#pragma unroll
    for (int i = 0; i < 32; i += 8)
        tile[ty + i][tx] = W[(size_t)(bk + ty + i) * 768 + bn + tx];
    __syncthreads();
#pragma unroll
    for (int i = 0; i < 32; i += 8)
        g_wprojT[(size_t)(bn + ty + i) * 768 + bk + tx] = __float2half(tile[tx][ty + i]);
}

// ---------------------------------------------------------------------------
// QKV GEMM (fp16 HMMA, cp.async double-buffered): M=4096, N=2304, K=768.
// ---------------------------------------------------------------------------
__global__ __launch_bounds__(256) void qkv_hgemm16(const float* __restrict__ bias) {
    extern __shared__ __half smq[];
    __half* As = smq;
    __half* Bs = smq + 10240;

    const int bm = blockIdx.y * 128, bn = blockIdx.x * 128;
    const int tid = threadIdx.x;
    const int w = tid >> 5, lane = tid & 31;
    const int g = lane >> 2, t = lane & 3;
    const int m0 = (w >> 1) * 32, n0 = (w & 1) * 64;

    float acc[2][8][4];
#pragma unroll
    for (int mi = 0; mi < 2; mi++)
#pragma unroll
        for (int nj = 0; nj < 8; nj++)
#pragma unroll
            for (int e = 0; e < 4; e++) acc[mi][nj][e] = 0.f;

#pragma unroll
    for (int i = 0; i < 2; i++) {
        int cdx = tid + i * 256;
        int row = cdx >> 2, off = (cdx & 3) * 8;
        cp_async16(As + row * 40 + off, g_x16 + (size_t)(bm + row) * 768 + off);
        cp_async16(Bs + row * 40 + off, g_wqkvT + (size_t)(bn + row) * 768 + off);
    }
    CP_COMMIT;

    for (int kt = 0; kt < 24; kt++) {
        const int cur = kt & 1;
        if (kt < 23) {
            int k0 = (kt + 1) * 32;
            __half* dA = As + (cur ^ 1) * 5120;
            __half* dB = Bs + (cur ^ 1) * 5120;
#pragma unroll
            for (int i = 0; i < 2; i++) {
                int cdx = tid + i * 256;
                int row = cdx >> 2, off = (cdx & 3) * 8;
                cp_async16(dA + row * 40 + off, g_x16 + (size_t)(bm + row) * 768 + k0 + off);
                cp_async16(dB + row * 40 + off, g_wqkvT + (size_t)(bn + row) * 768 + k0 + off);
            }
            CP_COMMIT;
            CP_WAIT(1);
        } else {
            CP_WAIT(0);
        }
        __syncthreads();

        const __half* Ab = As + cur * 5120;
        const __half* Bb = Bs + cur * 5120;
#pragma unroll
        for (int ks = 0; ks < 2; ks++) {
            unsigned a[2][4], b[8][2];
#pragma unroll
            for (int mi = 0; mi < 2; mi++) {
                int row = m0 + mi * 16 + g;
                int kk = ks * 16 + 2 * t;
                a[mi][0] = *(const unsigned*)&Ab[row * 40 + kk];
                a[mi][1] = *(const unsigned*)&Ab[(row + 8) * 40 + kk];
                a[mi][2] = *(const unsigned*)&Ab[row * 40 + kk + 8];
                a[mi][3] = *(const unsigned*)&Ab[(row + 8) * 40 + kk + 8];
            }
#pragma unroll
            for (int nj = 0; nj < 8; nj++) {
                int col = n0 + nj * 8 + g;
                int kk = ks * 16 + 2 * t;
                b[nj][0] = *(const unsigned*)&Bb[col * 40 + kk];
                b[nj][1] = *(const unsigned*)&Bb[col * 40 + kk + 8];
            }
#pragma unroll
            for (int mi = 0; mi < 2; mi++)
#pragma unroll
                for (int nj = 0; nj < 8; nj++)
                    mma16816(acc[mi][nj], a[mi], b[nj][0], b[nj][1]);
        }
        __syncthreads();
    }

#pragma unroll
    for (int mi = 0; mi < 2; mi++)
#pragma unroll
        for (int nj = 0; nj < 8; nj++)
#pragma unroll
            for (int e = 0; e < 4; e++) {
                int row = bm + m0 + mi * 16 + g + (e >> 1) * 8;
                int col = bn + n0 + nj * 8 + 2 * t + (e & 1);
                float val = acc[mi][nj][e] + bias[col];
                int which = col / 768;
                int rem = col - which * 768;
                int head = rem >> 6, d = rem & 63;
                size_t off = ((size_t)head * NQ + row) * HD + d;
                if (which == 0) g_q16[off] = __float2half(val);
                else if (which == 1) g_k16[off] = __float2half(val * SCALE_L2E);
                else g_v16[off] = __float2half(val);
            }
}

// ---------------------------------------------------------------------------
// proj GEMM (fp16 HMMA, cp.async double-buffered): M=4096, N=768.
// ---------------------------------------------------------------------------
__global__ __launch_bounds__(256) void proj_hgemm16(const float* __restrict__ bias,
                                                    float* __restrict__ out) {
    extern __shared__ __half smp[];
    __half* As = smp;
    __half* Bs = smp + 10240;

    const int bm = blockIdx.y * 128, bn = blockIdx.x * 128;
    const int tid = threadIdx.x;
    const int w = tid >> 5, lane = tid & 31;
    const int g = lane >> 2, t = lane & 3;
    const int m0 = (w >> 1) * 32, n0 = (w & 1) * 64;

    float acc[2][8][4];
#pragma unroll
    for (int mi = 0; mi < 2; mi++)
#pragma unroll
        for (int nj = 0; nj < 8; nj++)
#pragma unroll
            for (int e = 0; e < 4; e++) acc[mi][nj][e] = 0.f;

#pragma unroll
    for (int i = 0; i < 2; i++) {
        int cdx = tid + i * 256;
        int row = cdx >> 2, off = (cdx & 3) * 8;
        cp_async16(As + row * 40 + off, g_ao16 + (size_t)(bm + row) * 768 + off);
        cp_async16(Bs + row * 40 + off, g_wprojT + (size_t)(bn + row) * 768 + off);
    }
    CP_COMMIT;

    for (int kt = 0; kt < 24; kt++) {
        const int cur = kt & 1;
        if (kt < 23) {
            int k0 = (kt + 1) * 32;
            __half* dA = As + (cur ^ 1) * 5120;
            __half* dB = Bs + (cur ^ 1) * 5120;
#pragma unroll
            for (int i = 0; i < 2; i++) {
                int cdx = tid + i * 256;
                int row = cdx >> 2, off = (cdx & 3) * 8;
                cp_async16(dA + row * 40 + off, g_ao16 + (size_t)(bm + row) * 768 + k0 + off);
                cp_async16(dB + row * 40 + off, g_wprojT + (size_t)(bn + row) * 768 + k0 + off);
            }
            CP_COMMIT;
            CP_WAIT(1);
        } else {
            CP_WAIT(0);
        }
        __syncthreads();

        const __half* Ab = As + cur * 5120;
        const __half* Bb = Bs + cur * 5120;
#pragma unroll
        for (int ks = 0; ks < 2; ks++) {
            unsigned a[2][4], b[8][2];
#pragma unroll
            for (int mi = 0; mi < 2; mi++) {
                int row = m0 + mi * 16 + g;
                int kk = ks * 16 + 2 * t;
                a[mi][0] = *(const unsigned*)&Ab[row * 40 + kk];
                a[mi][1] = *(const unsigned*)&Ab[(row + 8) * 40 + kk];
                a[mi][2] = *(const unsigned*)&Ab[row * 40 + kk + 8];
                a[mi][3] = *(const unsigned*)&Ab[(row + 8) * 40 + kk + 8];
            }
#pragma unroll
            for (int nj = 0; nj < 8; nj++) {
                int col = n0 + nj * 8 + g;
                int kk = ks * 16 + 2 * t;
                b[nj][0] = *(const unsigned*)&Bb[col * 40 + kk];
                b[nj][1] = *(const unsigned*)&Bb[col * 40 + kk + 8];
            }
#pragma unroll
            for (int mi = 0; mi < 2; mi++)
#pragma unroll
                for (int nj = 0; nj < 8; nj++)
                    mma16816(acc[mi][nj], a[mi], b[nj][0], b[nj][1]);
        }
        __syncthreads();
    }

#pragma unroll
    for (int mi = 0; mi < 2; mi++)
#pragma unroll
        for (int nj = 0; nj < 8; nj++)
#pragma unroll
            for (int e2 = 0; e2 < 2; e2++) {
                int row = bm + m0 + mi * 16 + g + e2 * 8;
                int col = bn + n0 + nj * 8 + 2 * t;
                float2 v;
                v.x = acc[mi][nj][e2 * 2 + 0] + bias[col];
                v.y = acc[mi][nj][e2 * 2 + 1] + bias[col + 1];
                *(float2*)&out[(size_t)row * 768 + col] = v;
            }
}

// ---------------------------------------------------------------------------
// Tensor-core flash attention with fused rel-bias prologue.
// smem (halves): Qs[0,4608) | K 2x[4608,13824) | V 2x[13824,23040)
//                RWs[23040,27648) | RHs[27648,32256)
// prologue aliases (before K/V prefetch): Bh@4608, Bw@9216, P@4608 (pitch 136)
// ---------------------------------------------------------------------------
__global__ __launch_bounds__(128) void flash_attn(const float* __restrict__ rph,
                                                  const float* __restrict__ rpw) {
    extern __shared__ __half smd[];
    __half* Qs  = smd;                 // 4608
    __half* Ksh = smd + 4608;          // 2 x 4608
    __half* Vsh = smd + 13824;         // 2 x 4608
    __half* RWs = smd + 23040;         // 4608  [q][kw]  (xL2E)
    __half* RHs = smd + 27648;         // 4608  [q][kh]  (xL2E)

    const int qh = blockIdx.x, head = blockIdx.y;
    const int tid  = threadIdx.x;
    const int w    = tid >> 5;
    const int lane = tid & 31;
    const int g    = lane >> 2;
    const int t    = lane & 3;
    const int r0 = 16 * w + g;
    const int r1 = r0 + 8;

    const size_t qbase = ((size_t)head * NQ + qh * 64) * HD;
    const size_t hbase = (size_t)head * NQ * HD;

    const int mat = lane >> 3, mr = lane & 7;
    const unsigned smem_u32 = (unsigned)__cvta_generic_to_shared(smd);
    const unsigned kconst = ((mat >> 1) * 8 + mr) * 144 + (mat & 1) * 16;
    const unsigned vconst = ((mat & 1) * 8 + mr) * 144 + (mat >> 1) * 16;
    const unsigned kbase0 = smem_u32 + 4608 * 2 + kconst;
    const unsigned vbase0 = smem_u32 + 13824 * 2 + vconst;

    // ---- prologue phase 1: load Q, Bh, Bw ----
    {
        __half* Bh = smd + 4608;       // [64][72]: rph rows gathered by (qh-kh+63)
        __half* Bw = smd + 9216;       // [128][72]: rpw rows 0..126, row 127 = 0
        const unsigned* gq = (const unsigned*)(g_q16 + qbase);
        for (int i = tid; i < 2048; i += 128) {
            int r = i >> 5, c2 = i & 31;
            *(unsigned*)&Qs[r * 72 + c2 * 2] = gq[i];
        }
        for (int i = tid; i < 4096; i += 128) {
            int kh = i >> 6, c = i & 63;
            Bh[kh * 72 + c] = __float2half(rph[(qh - kh + 63) * 64 + c]);
        }
        for (int i = tid; i < 127 * 64; i += 128) {
            int r = i >> 6, c = i & 63;
            Bw[r * 72 + c] = __float2half(rpw[i]);
        }
        if (tid < 64) Bw[127 * 72 + tid] = __float2half(0.f);
    }
    __syncthreads();

    // ---- Q fragments (shared by prologue GEMMs and main loop) ----
    unsigned qa[4][4];
#pragma unroll
    for (int u = 0; u < 4; u++) {
        int d = 16 * u + 2 * t;
        qa[u][0] = *(const unsigned*)&Qs[r0 * 72 + d];
        qa[u][1] = *(const unsigned*)&Qs[r1 * 72 + d];
        qa[u][2] = *(const unsigned*)&Qs[r0 * 72 + d + 8];
        qa[u][3] = *(const unsigned*)&Qs[r1 * 72 + d + 8];
    }

    // ---- prologue phase 2: RH = Q @ Bh^T  (store xL2E into RHs) ----
    {
        float ch[8][4];
#pragma unroll
        for (int j = 0; j < 8; j++)
#pragma unroll
            for (int e = 0; e < 4; e++) ch[j][e] = 0.f;
        const unsigned bhb = smem_u32 + 4608 * 2 + kconst;
#pragma unroll
        for (int u = 0; u < 4; u++)
#pragma unroll
            for (int j2 = 0; j2 < 4; j2++) {
                unsigned b0, b1, b2, b3;
                ldsm4(b0, b1, b2, b3, bhb + j2 * 2304 + u * 32);
                mma16816(ch[2 * j2],     qa[u], b0, b1);
                mma16816(ch[2 * j2 + 1], qa[u], b2, b3);
            }
#pragma unroll
        for (int j = 0; j < 8; j++) {
            int col = 8 * j + 2 * t;
            *(unsigned*)&RHs[r0 * 72 + col] = f2h2(ch[j][0] * L2E, ch[j][1] * L2E);
            *(unsigned*)&RHs[r1 * 72 + col] = f2h2(ch[j][2] * L2E, ch[j][3] * L2E);
        }
    }

    // ---- prologue phase 3: P = Q @ Bw^T, gather RWs[q][kw] = P[q][q-kw+63] ----
    {
        float cp[16][4];
#pragma unroll
        for (int j = 0; j < 16; j++)
#pragma unroll
            for (int e = 0; e < 4; e++) cp[j][e] = 0.f;
        const unsigned bwb = smem_u32 + 9216 * 2 + kconst;
#pragma unroll
        for (int u = 0; u < 4; u++)
#pragma unroll
            for (int j2 = 0; j2 < 8; j2++) {
                unsigned b0, b1, b2, b3;
                ldsm4(b0, b1, b2, b3, bwb + j2 * 2304 + u * 32);
                mma16816(cp[2 * j2],     qa[u], b0, b1);
                mma16816(cp[2 * j2 + 1], qa[u], b2, b3);
            }
        __syncthreads();   // all ldsm reads of Bh/Bw complete before overwrite

        __half* Psm = smd + 4608;      // [64][136], aliases Bh/Bw region
#pragma unroll
        for (int nj = 0; nj < 16; nj++) {
            int col = 8 * nj + 2 * t;
            *(unsigned*)&Psm[r0 * 136 + col] = f2h2(cp[nj][0] * L2E, cp[nj][1] * L2E);
            *(unsigned*)&Psm[r1 * 136 + col] = f2h2(cp[nj][2] * L2E, cp[nj][3] * L2E);
        }
        __syncthreads();

        for (int i = tid; i < 4096; i += 128) {
            int q = i >> 6, kw = i & 63;
            RWs[q * 72 + kw] = Psm[q * 136 + (q - kw + 63)];
        }
    }
    __syncthreads();       // gather done before K/V prefetch overwrites region

    // ---- prefetch key tile 0 ----
    {
        const __half* gk = g_k16 + hbase;
        const __half* gv = g_v16 + hbase;
#pragma unroll
        for (int i = 0; i < 4; i++) {
            int c = tid + i * 128;
            int key = c >> 3, off = (c & 7) * 8;
            cp_async16(&Ksh[key * 72 + off], gk + c * 8);
            cp_async16(&Vsh[key * 72 + off], gv + c * 8);
        }
        CP_COMMIT;
    }

    float o[8][4];
#pragma unroll
    for (int j = 0; j < 8; j++)
#pragma unroll
        for (int e = 0; e < 4; e++) o[j][e] = 0.f;
    float m0 = -1e30f, m1 = -1e30f, l0 = 0.f, l1 = 0.f;

    for (int kt = 0; kt < 64; kt++) {
        const int cur = kt & 1;
        if (kt < 63) {
            const __half* gk = g_k16 + hbase + (size_t)(kt + 1) * 4096;
            const __half* gv = g_v16 + hbase + (size_t)(kt + 1) * 4096;
            __half* dk = Ksh + (cur ^ 1) * 4608;
            __half* dv = Vsh + (cur ^ 1) * 4608;
#pragma unroll
            for (int i = 0; i < 4; i++) {
                int c = tid + i * 128;
                int key = c >> 3, off = (c & 7) * 8;
                cp_async16(&dk[key * 72 + off], gk + c * 8);
                cp_async16(&dv[key * 72 + off], gv + c * 8);
            }
            CP_COMMIT;
            CP_WAIT(1);
        } else {
            CP_WAIT(0);
        }
        __syncthreads();

        float c[8][4];
#pragma unroll
        for (int j = 0; j < 8; j++)
#pragma unroll
            for (int e = 0; e < 4; e++) c[j][e] = 0.f;
        {
            const unsigned kb = kbase0 + cur * 9216 + kconst - kconst + cur * 0;  // keep simple
        }
        {
            const unsigned kb = kbase0 + cur * 9216;
#pragma unroll
            for (int u = 0; u < 4; u++) {
#pragma unroll
                for (int j2 = 0; j2 < 4; j2++) {
                    unsigned b0, b1, b2, b3;
                    ldsm4(b0, b1, b2, b3, kb + j2 * 2304 + u * 32);
                    mma16816(c[2 * j2],     qa[u], b0, b1);
                    mma16816(c[2 * j2 + 1], qa[u], b2, b3);
                }
            }
        }

        float rh0 = __half2float(RHs[r0 * 72 + kt]);
        float rh1 = __half2float(RHs[r1 * 72 + kt]);
#pragma unroll
        for (int j = 0; j < 8; j++) {
            int col = 8 * j + 2 * t;
            float2 w0 = __half22float2(*(const __half2*)&RWs[r0 * 72 + col]);
            float2 w1 = __half22float2(*(const __half2*)&RWs[r1 * 72 + col]);
            c[j][0] += rh0 + w0.x;
            c[j][1] += rh0 + w0.y;
            c[j][2] += rh1 + w1.x;
            c[j][3] += rh1 + w1.y;
        }

        float mx0 = -1e30f, mx1 = -1e30f;
#pragma unroll
        for (int j = 0; j < 8; j++) {
            mx0 = fmaxf(mx0, fmaxf(c[j][0], c[j][1]));
            mx1 = fmaxf(mx1, fmaxf(c[j][2], c[j][3]));
        }
        mx0 = fmaxf(mx0, __shfl_xor_sync(0xffffffffu, mx0, 1));
        mx0 = fmaxf(mx0, __shfl_xor_sync(0xffffffffu, mx0, 2));
        mx1 = fmaxf(mx1, __shfl_xor_sync(0xffffffffu, mx1, 1));
        mx1 = fmaxf(mx1, __shfl_xor_sync(0xffffffffu, mx1, 2));

        float mn0 = fmaxf(m0, mx0), mn1 = fmaxf(m1, mx1);
        float al0 = ex2f(m0 - mn0), al1 = ex2f(m1 - mn1);
        m0 = mn0; m1 = mn1;

        float s0 = 0.f, s1 = 0.f;
#pragma unroll
        for (int j = 0; j < 8; j++) {
            c[j][0] = ex2f(c[j][0] - mn0); s0 += c[j][0];
            c[j][1] = ex2f(c[j][1] - mn0); s0 += c[j][1];
            c[j][2] = ex2f(c[j][2] - mn1); s1 += c[j][2];
            c[j][3] = ex2f(c[j][3] - mn1); s1 += c[j][3];
        }
        s0 += __shfl_xor_sync(0xffffffffu, s0, 1);
        s0 += __shfl_xor_sync(0xffffffffu, s0, 2);
        s1 += __shfl_xor_sync(0xffffffffu, s1, 1);
        s1 += __shfl_xor_sync(0xffffffffu, s1, 2);
        l0 = l0 * al0 + s0;
        l1 = l1 * al1 + s1;

#pragma unroll
        for (int j = 0; j < 8; j++) {
            o[j][0] *= al0; o[j][1] *= al0;
            o[j][2] *= al1; o[j][3] *= al1;
        }

        {
            const unsigned vb = vbase0 + cur * 9216;
#pragma unroll
            for (int u = 0; u < 4; u++) {
                unsigned pa[4];
                pa[0] = f2h2(c[2 * u][0], c[2 * u][1]);
                pa[1] = f2h2(c[2 * u][2], c[2 * u][3]);
                pa[2] = f2h2(c[2 * u + 1][0], c[2 * u + 1][1]);
                pa[3] = f2h2(c[2 * u + 1][2], c[2 * u + 1][3]);
#pragma unroll
                for (int j2 = 0; j2 < 4; j2++) {
                    unsigned b0, b1, b2, b3;
                    ldsm4t(b0, b1, b2, b3, vb + u * 2304 + j2 * 32);
                    mma16816(o[2 * j2],     pa, b0, b1);
                    mma16816(o[2 * j2 + 1], pa, b2, b3);
                }
            }
        }
        __syncthreads();
    }

    float inv0 = 1.f / l0, inv1 = 1.f / l1;
    __half* outp = g_ao16 + (size_t)(qh * 64) * CDIM + head * 64;
#pragma unroll
    for (int j = 0; j < 8; j++) {
        int col = 8 * j + 2 * t;
        *(__half2*)&outp[(size_t)r0 * CDIM + col] =
            __floats2half2_rn(o[j][0] * inv0, o[j][1] * inv0);
        *(__half2*)&outp[(size_t)r1 * CDIM + col] =
            __floats2half2_rn(o[j][2] * inv1, o[j][3] * inv1);
    }
}

// ---------------------------------------------------------------------------
extern "C" void kernel_launch(void* const* d_in, const int* in_sizes, int n_in,
                              void* d_out, int out_size) {
    const float* x      = (const float*)d_in[0];
    const float* qkv_w  = (const float*)d_in[1];
    const float* qkv_b  = (const float*)d_in[2];
    const float* proj_w = (const float*)d_in[3];
    const float* proj_b = (const float*)d_in[4];
    const float* rph    = (const float*)d_in[5];
    const float* rpw    = (const float*)d_in[6];
    float* out = (float*)d_out;

    const int GEMM_SMEM  = 20480 * 2;   // 40960 B
    const int FLASH_SMEM = 32256 * 2;   // 64512 B
    cudaFuncSetAttribute(flash_attn, cudaFuncAttributeMaxDynamicSharedMemorySize, FLASH_SMEM);

    conv_x_kernel<<<(NQ * CDIM / 4 + 255) / 256, 256>>>(x);
    transpose_qkv_kernel<<<dim3(72, 24), dim3(32, 8)>>>(qkv_w);
    transpose_proj_kernel<<<dim3(24, 24), dim3(32, 8)>>>(proj_w);
    qkv_hgemm16<<<dim3(18, 32), 256, GEMM_SMEM>>>(qkv_b);
    flash_attn<<<dim3(64, 12), 128, FLASH_SMEM>>>(rph, rpw);
    proj_hgemm16<<<dim3(6, 32), 256, GEMM_SMEM>>>(proj_b, out);
}

// round 9
// speedup vs baseline: 6.8074x; 1.0206x over previous
#include <cuda_runtime.h>
#include <cuda_fp16.h>

// SAM Vision Attention: B=1, H=W=64, N=4096, C=768, nh=12, hd=64
// R9: flash_attn processes 128 queries (2 image rows) per CTA with 8 warps:
//     halves K/V traffic, raises warps/SM 12->16, CTAs 768->384.

#define NH 12
#define NQ 4096
#define HD 64
#define CDIM 768
#define L2E 1.44269504f
#define SCALE_L2E (0.125f * 1.44269504f)   // 64^-0.5 * log2(e), folded into k

__device__ __half g_q16[NH * NQ * HD];
__device__ __half g_k16[NH * NQ * HD];        // pre-scaled by SCALE_L2E
__device__ __half g_v16[NH * NQ * HD];
__device__ __half g_ao16[NQ * CDIM];          // attention output (proj A input)
__device__ __half g_x16[NQ * CDIM];           // x in fp16
__device__ __half g_wqkvT[3 * CDIM * CDIM];   // qkv_w^T  [2304][768] fp16
__device__ __half g_wprojT[CDIM * CDIM];      // proj_w^T [768][768] fp16

// ---------------------------------------------------------------------------
// helpers
// ---------------------------------------------------------------------------
__device__ __forceinline__ void mma16816(float* c, const unsigned* a,
                                         unsigned b0, unsigned b1) {
    asm volatile(
        "mma.sync.aligned.m16n8k16.row.col.f32.f16.f16.f32 "
        "{%0,%1,%2,%3}, {%4,%5,%6,%7}, {%8,%9}, {%0,%1,%2,%3};\n"
        : "+f"(c[0]), "+f"(c[1]), "+f"(c[2]), "+f"(c[3])
        : "r"(a[0]), "r"(a[1]), "r"(a[2]), "r"(a[3]), "r"(b0), "r"(b1));
}

__device__ __forceinline__ unsigned f2h2(float x, float y) {
    __half2 h = __floats2half2_rn(x, y);
    return *(unsigned*)&h;
}

__device__ __forceinline__ float ex2f(float x) {
    float y;
    asm("ex2.approx.f32 %0, %1;" : "=f"(y) : "f"(x));
    return y;
}

__device__ __forceinline__ void cp_async16(void* dst, const void* src) {
    unsigned d = (unsigned)__cvta_generic_to_shared(dst);
    asm volatile("cp.async.cg.shared.global [%0], [%1], 16;\n" :: "r"(d), "l"(src));
}
#define CP_COMMIT asm volatile("cp.async.commit_group;\n")
#define CP_WAIT(n) asm volatile("cp.async.wait_group %0;\n" :: "n"(n))

__device__ __forceinline__ void ldsm4(unsigned& r0, unsigned& r1, unsigned& r2,
                                      unsigned& r3, unsigned a) {
    asm volatile("ldmatrix.sync.aligned.m8n8.x4.shared.b16 {%0,%1,%2,%3}, [%4];"
                 : "=r"(r0), "=r"(r1), "=r"(r2), "=r"(r3) : "r"(a));
}
__device__ __forceinline__ void ldsm4t(unsigned& r0, unsigned& r1, unsigned& r2,
                                       unsigned& r3, unsigned a) {
    asm volatile("ldmatrix.sync.aligned.m8n8.x4.trans.shared.b16 {%0,%1,%2,%3}, [%4];"
                 : "=r"(r0), "=r"(r1), "=r"(r2), "=r"(r3) : "r"(a));
}

// ---------------------------------------------------------------------------
// one-time conversion kernels (globals referenced from device code only)
// ---------------------------------------------------------------------------
__global__ void conv_x_kernel(const float* __restrict__ X) {
    int i = blockIdx.x * 256 + threadIdx.x;
    if (i < NQ * CDIM / 4) {
        float4 v = ((const float4*)X)[i];
        __half2* o = (__half2*)(g_x16 + i * 4);
        o[0] = __floats2half2_rn(v.x, v.y);
        o[1] = __floats2half2_rn(v.z, v.w);
    }
}

__global__ void transpose_qkv_kernel(const float* __restrict__ W) {
    __shared__ float tile[32][33];
    int bn = blockIdx.x * 32, bk = blockIdx.y * 32;
    int tx = threadIdx.x, ty = threadIdx.y;
#pragma unroll
    for (int i = 0; i < 32; i += 8)
        tile[ty + i][tx] = W[(size_t)(bk + ty + i) * 2304 + bn + tx];
    __syncthreads();
#pragma unroll
    for (int i = 0; i < 32; i += 8)
        g_wqkvT[(size_t)(bn + ty + i) * 768 + bk + tx] = __float2half(tile[tx][ty + i]);
}

__global__ void transpose_proj_kernel(const float* __restrict__ W) {
    __shared__ float tile[32][33];
    int bn = blockIdx.x * 32, bk = blockIdx.y * 32;
    int tx = threadIdx.x, ty = threadIdx.y;
#pragma unroll
    for (int i = 0; i < 32; i += 8)
        tile[ty + i][tx] = W[(size_t)(bk + ty + i) * 768 + bn + tx];
    __syncthreads();
#pragma unroll
    for (int i = 0; i < 32; i += 8)
        g_wprojT[(size_t)(bn + ty + i) * 768 + bk + tx] = __float2half(tile[tx][ty + i]);
}

// ---------------------------------------------------------------------------
// QKV GEMM (fp16 HMMA, cp.async double-buffered): M=4096, N=2304, K=768.
// ---------------------------------------------------------------------------
__global__ __launch_bounds__(256) void qkv_hgemm16(const float* __restrict__ bias) {
    extern __shared__ __half smq[];
    __half* As = smq;
    __half* Bs = smq + 10240;

    const int bm = blockIdx.y * 128, bn = blockIdx.x * 128;
    const int tid = threadIdx.x;
    const int w = tid >> 5, lane = tid & 31;
    const int g = lane >> 2, t = lane & 3;
    const int m0 = (w >> 1) * 32, n0 = (w & 1) * 64;

    float acc[2][8][4];
#pragma unroll
    for (int mi = 0; mi < 2; mi++)
#pragma unroll
        for (int nj = 0; nj < 8; nj++)
#pragma unroll
            for (int e = 0; e < 4; e++) acc[mi][nj][e] = 0.f;

#pragma unroll
    for (int i = 0; i < 2; i++) {
        int cdx = tid + i * 256;
        int row = cdx >> 2, off = (cdx & 3) * 8;
        cp_async16(As + row * 40 + off, g_x16 + (size_t)(bm + row) * 768 + off);
        cp_async16(Bs + row * 40 + off, g_wqkvT + (size_t)(bn + row) * 768 + off);
    }
    CP_COMMIT;

    for (int kt = 0; kt < 24; kt++) {
        const int cur = kt & 1;
        if (kt < 23) {
            int k0 = (kt + 1) * 32;
            __half* dA = As + (cur ^ 1) * 5120;
            __half* dB = Bs + (cur ^ 1) * 5120;
#pragma unroll
            for (int i = 0; i < 2; i++) {
                int cdx = tid + i * 256;
                int row = cdx >> 2, off = (cdx & 3) * 8;
                cp_async16(dA + row * 40 + off, g_x16 + (size_t)(bm + row) * 768 + k0 + off);
                cp_async16(dB + row * 40 + off, g_wqkvT + (size_t)(bn + row) * 768 + k0 + off);
            }
            CP_COMMIT;
            CP_WAIT(1);
        } else {
            CP_WAIT(0);
        }
        __syncthreads();

        const __half* Ab = As + cur * 5120;
        const __half* Bb = Bs + cur * 5120;
#pragma unroll
        for (int ks = 0; ks < 2; ks++) {
            unsigned a[2][4], b[8][2];
#pragma unroll
            for (int mi = 0; mi < 2; mi++) {
                int row = m0 + mi * 16 + g;
                int kk = ks * 16 + 2 * t;
                a[mi][0] = *(const unsigned*)&Ab[row * 40 + kk];
                a[mi][1] = *(const unsigned*)&Ab[(row + 8) * 40 + kk];
                a[mi][2] = *(const unsigned*)&Ab[row * 40 + kk + 8];
                a[mi][3] = *(const unsigned*)&Ab[(row + 8) * 40 + kk + 8];
            }
#pragma unroll
            for (int nj = 0; nj < 8; nj++) {
                int col = n0 + nj * 8 + g;
                int kk = ks * 16 + 2 * t;
                b[nj][0] = *(const unsigned*)&Bb[col * 40 + kk];
                b[nj][1] = *(const unsigned*)&Bb[col * 40 + kk + 8];
            }
#pragma unroll
            for (int mi = 0; mi < 2; mi++)
#pragma unroll
                for (int nj = 0; nj < 8; nj++)
                    mma16816(acc[mi][nj], a[mi], b[nj][0], b[nj][1]);
        }
        __syncthreads();
    }

#pragma unroll
    for (int mi = 0; mi < 2; mi++)
#pragma unroll
        for (int nj = 0; nj < 8; nj++)
#pragma unroll
            for (int e = 0; e < 4; e++) {
                int row = bm + m0 + mi * 16 + g + (e >> 1) * 8;
                int col = bn + n0 + nj * 8 + 2 * t + (e & 1);
                float val = acc[mi][nj][e] + bias[col];
                int which = col / 768;
                int rem = col - which * 768;
                int head = rem >> 6, d = rem & 63;
                size_t off = ((size_t)head * NQ + row) * HD + d;
                if (which == 0) g_q16[off] = __float2half(val);
                else if (which == 1) g_k16[off] = __float2half(val * SCALE_L2E);
                else g_v16[off] = __float2half(val);
            }
}

// ---------------------------------------------------------------------------
// proj GEMM (fp16 HMMA, cp.async double-buffered): M=4096, N=768.
// ---------------------------------------------------------------------------
__global__ __launch_bounds__(256) void proj_hgemm16(const float* __restrict__ bias,
                                                    float* __restrict__ out) {
    extern __shared__ __half smp[];
    __half* As = smp;
    __half* Bs = smp + 10240;

    const int bm = blockIdx.y * 128, bn = blockIdx.x * 128;
    const int tid = threadIdx.x;
    const int w = tid >> 5, lane = tid & 31;
    const int g = lane >> 2, t = lane & 3;
    const int m0 = (w >> 1) * 32, n0 = (w & 1) * 64;

    float acc[2][8][4];
#pragma unroll
    for (int mi = 0; mi < 2; mi++)
#pragma unroll
        for (int nj = 0; nj < 8; nj++)
#pragma unroll
            for (int e = 0; e < 4; e++) acc[mi][nj][e] = 0.f;

#pragma unroll
    for (int i = 0; i < 2; i++) {
        int cdx = tid + i * 256;
        int row = cdx >> 2, off = (cdx & 3) * 8;
        cp_async16(As + row * 40 + off, g_ao16 + (size_t)(bm + row) * 768 + off);
        cp_async16(Bs + row * 40 + off, g_wprojT + (size_t)(bn + row) * 768 + off);
    }
    CP_COMMIT;

    for (int kt = 0; kt < 24; kt++) {
        const int cur = kt & 1;
        if (kt < 23) {
            int k0 = (kt + 1) * 32;
            __half* dA = As + (cur ^ 1) * 5120;
            __half* dB = Bs + (cur ^ 1) * 5120;
#pragma unroll
            for (int i = 0; i < 2; i++) {
                int cdx = tid + i * 256;
                int row = cdx >> 2, off = (cdx & 3) * 8;
                cp_async16(dA + row * 40 + off, g_ao16 + (size_t)(bm + row) * 768 + k0 + off);
                cp_async16(dB + row * 40 + off, g_wprojT + (size_t)(bn + row) * 768 + k0 + off);
            }
            CP_COMMIT;
            CP_WAIT(1);
        } else {
            CP_WAIT(0);
        }
        __syncthreads();

        const __half* Ab = As + cur * 5120;
        const __half* Bb = Bs + cur * 5120;
#pragma unroll
        for (int ks = 0; ks < 2; ks++) {
            unsigned a[2][4], b[8][2];
#pragma unroll
            for (int mi = 0; mi < 2; mi++) {
                int row = m0 + mi * 16 + g;
                int kk = ks * 16 + 2 * t;
                a[mi][0] = *(const unsigned*)&Ab[row * 40 + kk];
                a[mi][1] = *(const unsigned*)&Ab[(row + 8) * 40 + kk];
                a[mi][2] = *(const unsigned*)&Ab[row * 40 + kk + 8];
                a[mi][3] = *(const unsigned*)&Ab[(row + 8) * 40 + kk + 8];
            }
#pragma unroll
            for (int nj = 0; nj < 8; nj++) {
                int col = n0 + nj * 8 + g;
                int kk = ks * 16 + 2 * t;
                b[nj][0] = *(const unsigned*)&Bb[col * 40 + kk];
                b[nj][1] = *(const unsigned*)&Bb[col * 40 + kk + 8];
            }
#pragma unroll
            for (int mi = 0; mi < 2; mi++)
#pragma unroll
                for (int nj = 0; nj < 8; nj++)
                    mma16816(acc[mi][nj], a[mi], b[nj][0], b[nj][1]);
        }
        __syncthreads();
    }

#pragma unroll
    for (int mi = 0; mi < 2; mi++)
#pragma unroll
        for (int nj = 0; nj < 8; nj++)
#pragma unroll
            for (int e2 = 0; e2 < 2; e2++) {
                int row = bm + m0 + mi * 16 + g + e2 * 8;
                int col = bn + n0 + nj * 8 + 2 * t;
                float2 v;
                v.x = acc[mi][nj][e2 * 2 + 0] + bias[col];
                v.y = acc[mi][nj][e2 * 2 + 1] + bias[col + 1];
                *(float2*)&out[(size_t)row * 768 + col] = v;
            }
}

// ---------------------------------------------------------------------------
// Flash attention: 128 queries (2 image rows qh0, qh0+1) per CTA, 8 warps.
// smem (halves): Qs[0,9216) | K 2x[9216,18432) | V 2x[18432,27648)
//                RWs[27648,36864) | RHs[36864,46080)        = 92160 B
// prologue aliases (K/V region): Bh[2][64][72]@9216, Bw[128][72]@18432,
//                                P[128][136]@9216
// ---------------------------------------------------------------------------
__global__ __launch_bounds__(256, 2) void flash_attn(const float* __restrict__ rph,
                                                     const float* __restrict__ rpw) {
    extern __shared__ __half smd[];
    __half* Qs  = smd;                 // [128][72]
    __half* Ksh = smd + 9216;          // 2 x [64][72]
    __half* Vsh = smd + 18432;         // 2 x [64][72]
    __half* RWs = smd + 27648;         // [128][72]  (xL2E)
    __half* RHs = smd + 36864;         // [128][72]  (xL2E)

    const int bx = blockIdx.x;         // 0..31: query rows [bx*128, bx*128+128)
    const int head = blockIdx.y;
    const int qh0 = bx * 2;
    const int tid  = threadIdx.x;
    const int w    = tid >> 5;         // 0..7
    const int lane = tid & 31;
    const int g    = lane >> 2;
    const int t    = lane & 3;
    const int r0 = 16 * w + g;         // block-local query rows 0..127
    const int r1 = r0 + 8;

    const size_t qbase = ((size_t)head * NQ + bx * 128) * HD;
    const size_t hbase = (size_t)head * NQ * HD;

    const int mat = lane >> 3, mr = lane & 7;
    const unsigned smem_u32 = (unsigned)__cvta_generic_to_shared(smd);
    const unsigned kconst = ((mat >> 1) * 8 + mr) * 144 + (mat & 1) * 16;
    const unsigned vconst = ((mat & 1) * 8 + mr) * 144 + (mat >> 1) * 16;
    const unsigned kbase0 = smem_u32 + 9216 * 2 + kconst;
    const unsigned vbase0 = smem_u32 + 18432 * 2 + vconst;

    // ---- prologue phase 1: load Q, Bh (two tables), Bw ----
    {
        __half* Bh = smd + 9216;       // [2][64][72]
        __half* Bw = smd + 18432;      // [128][72], row 127 = 0
        const unsigned* gq = (const unsigned*)(g_q16 + qbase);
        for (int i = tid; i < 4096; i += 256) {
            int r = i >> 5, c2 = i & 31;
            *(unsigned*)&Qs[r * 72 + c2 * 2] = gq[i];
        }
        for (int i = tid; i < 8192; i += 256) {
            int h = i >> 12, j = i & 4095;
            int kh = j >> 6, c = j & 63;
            Bh[h * 4608 + kh * 72 + c] = __float2half(rph[(qh0 + h - kh + 63) * 64 + c]);
        }
        for (int i = tid; i < 127 * 64; i += 256) {
            int r = i >> 6, c = i & 63;
            Bw[r * 72 + c] = __float2half(rpw[i]);
        }
        if (tid < 64) Bw[127 * 72 + tid] = __float2half(0.f);
    }
    __syncthreads();

    // ---- Q fragments (shared by prologue GEMMs and main loop) ----
    unsigned qa[4][4];
#pragma unroll
    for (int u = 0; u < 4; u++) {
        int d = 16 * u + 2 * t;
        qa[u][0] = *(const unsigned*)&Qs[r0 * 72 + d];
        qa[u][1] = *(const unsigned*)&Qs[r1 * 72 + d];
        qa[u][2] = *(const unsigned*)&Qs[r0 * 72 + d + 8];
        qa[u][3] = *(const unsigned*)&Qs[r1 * 72 + d + 8];
    }

    // ---- prologue phase 2: RH = Q @ Bh[w>>2]^T  (xL2E into RHs) ----
    {
        float ch[8][4];
#pragma unroll
        for (int j = 0; j < 8; j++)
#pragma unroll
            for (int e = 0; e < 4; e++) ch[j][e] = 0.f;
        const unsigned bhb = smem_u32 + (9216 + (w >> 2) * 4608) * 2 + kconst;
#pragma unroll
        for (int u = 0; u < 4; u++)
#pragma unroll
            for (int j2 = 0; j2 < 4; j2++) {
                unsigned b0, b1, b2, b3;
                ldsm4(b0, b1, b2, b3, bhb + j2 * 2304 + u * 32);
                mma16816(ch[2 * j2],     qa[u], b0, b1);
                mma16816(ch[2 * j2 + 1], qa[u], b2, b3);
            }
#pragma unroll
        for (int j = 0; j < 8; j++) {
            int col = 8 * j + 2 * t;
            *(unsigned*)&RHs[r0 * 72 + col] = f2h2(ch[j][0] * L2E, ch[j][1] * L2E);
            *(unsigned*)&RHs[r1 * 72 + col] = f2h2(ch[j][2] * L2E, ch[j][3] * L2E);
        }
    }

    // ---- prologue phase 3: P = Q @ Bw^T, gather RWs[q][kw] = P[q][qw-kw+63] ----
    {
        float cp[16][4];
#pragma unroll
        for (int j = 0; j < 16; j++)
#pragma unroll
            for (int e = 0; e < 4; e++) cp[j][e] = 0.f;
        const unsigned bwb = smem_u32 + 18432 * 2 + kconst;
#pragma unroll
        for (int u = 0; u < 4; u++)
#pragma unroll
            for (int j2 = 0; j2 < 8; j2++) {
                unsigned b0, b1, b2, b3;
                ldsm4(b0, b1, b2, b3, bwb + j2 * 2304 + u * 32);
                mma16816(cp[2 * j2],     qa[u], b0, b1);
                mma16816(cp[2 * j2 + 1], qa[u], b2, b3);
            }
        __syncthreads();   // all ldsm reads of Bh/Bw complete before overwrite

        __half* Psm = smd + 9216;      // [128][136], aliases Bh/Bw region
#pragma unroll
        for (int nj = 0; nj < 16; nj++) {
            int col = 8 * nj + 2 * t;
            *(unsigned*)&Psm[r0 * 136 + col] = f2h2(cp[nj][0] * L2E, cp[nj][1] * L2E);
            *(unsigned*)&Psm[r1 * 136 + col] = f2h2(cp[nj][2] * L2E, cp[nj][3] * L2E);
        }
        __syncthreads();

        for (int i = tid; i < 8192; i += 256) {
            int q = i >> 6, kw = i & 63;
            RWs[q * 72 + kw] = Psm[q * 136 + ((q & 63) - kw + 63)];
        }
    }
    __syncthreads();       // gather done before K/V prefetch overwrites region

    // ---- prefetch key tile 0 ----
    {
        const __half* gk = g_k16 + hbase;
        const __half* gv = g_v16 + hbase;
#pragma unroll
        for (int i = 0; i < 2; i++) {
            int c = tid + i * 256;
            int key = c >> 3, off = (c & 7) * 8;
            cp_async16(&Ksh[key * 72 + off], gk + c * 8);
            cp_async16(&Vsh[key * 72 + off], gv + c * 8);
        }
        CP_COMMIT;
    }

    float o[8][4];
#pragma unroll
    for (int j = 0; j < 8; j++)
#pragma unroll
        for (int e = 0; e < 4; e++) o[j][e] = 0.f;
    float m0 = -1e30f, m1 = -1e30f, l0 = 0.f, l1 = 0.f;

    for (int kt = 0; kt < 64; kt++) {
        const int cur = kt & 1;
        if (kt < 63) {
            const __half* gk = g_k16 + hbase + (size_t)(kt + 1) * 4096;
            const __half* gv = g_v16 + hbase + (size_t)(kt + 1) * 4096;
            __half* dk = Ksh + (cur ^ 1) * 4608;
            __half* dv = Vsh + (cur ^ 1) * 4608;
#pragma unroll
            for (int i = 0; i < 2; i++) {
                int c = tid + i * 256;
                int key = c >> 3, off = (c & 7) * 8;
                cp_async16(&dk[key * 72 + off], gk + c * 8);
                cp_async16(&dv[key * 72 + off], gv + c * 8);
            }
            CP_COMMIT;
            CP_WAIT(1);
        } else {
            CP_WAIT(0);
        }
        __syncthreads();

        // ---- S = Q @ K^T ----
        float c[8][4];
#pragma unroll
        for (int j = 0; j < 8; j++)
#pragma unroll
            for (int e = 0; e < 4; e++) c[j][e] = 0.f;
        {
            const unsigned kb = kbase0 + cur * 9216;
#pragma unroll
            for (int u = 0; u < 4; u++) {
#pragma unroll
                for (int j2 = 0; j2 < 4; j2++) {
                    unsigned b0, b1, b2, b3;
                    ldsm4(b0, b1, b2, b3, kb + j2 * 2304 + u * 32);
                    mma16816(c[2 * j2],     qa[u], b0, b1);
                    mma16816(c[2 * j2 + 1], qa[u], b2, b3);
                }
            }
        }

        // ---- bias (already xL2E) ----
        float rh0 = __half2float(RHs[r0 * 72 + kt]);
        float rh1 = __half2float(RHs[r1 * 72 + kt]);
#pragma unroll
        for (int j = 0; j < 8; j++) {
            int col = 8 * j + 2 * t;
            float2 w0 = __half22float2(*(const __half2*)&RWs[r0 * 72 + col]);
            float2 w1 = __half22float2(*(const __half2*)&RWs[r1 * 72 + col]);
            c[j][0] += rh0 + w0.x;
            c[j][1] += rh0 + w0.y;
            c[j][2] += rh1 + w1.x;
            c[j][3] += rh1 + w1.y;
        }

        // ---- online softmax (base-2) ----
        float mx0 = -1e30f, mx1 = -1e30f;
#pragma unroll
        for (int j = 0; j < 8; j++) {
            mx0 = fmaxf(mx0, fmaxf(c[j][0], c[j][1]));
            mx1 = fmaxf(mx1, fmaxf(c[j][2], c[j][3]));
        }
        mx0 = fmaxf(mx0, __shfl_xor_sync(0xffffffffu, mx0, 1));
        mx0 = fmaxf(mx0, __shfl_xor_sync(0xffffffffu, mx0, 2));
        mx1 = fmaxf(mx1, __shfl_xor_sync(0xffffffffu, mx1, 1));
        mx1 = fmaxf(mx1, __shfl_xor_sync(0xffffffffu, mx1, 2));

        float mn0 = fmaxf(m0, mx0), mn1 = fmaxf(m1, mx1);
        float al0 = ex2f(m0 - mn0), al1 = ex2f(m1 - mn1);
        m0 = mn0; m1 = mn1;

        float s0 = 0.f, s1 = 0.f;
#pragma unroll
        for (int j = 0; j < 8; j++) {
            c[j][0] = ex2f(c[j][0] - mn0); s0 += c[j][0];
            c[j][1] = ex2f(c[j][1] - mn0); s0 += c[j][1];
            c[j][2] = ex2f(c[j][2] - mn1); s1 += c[j][2];
            c[j][3] = ex2f(c[j][3] - mn1); s1 += c[j][3];
        }
        s0 += __shfl_xor_sync(0xffffffffu, s0, 1);
        s0 += __shfl_xor_sync(0xffffffffu, s0, 2);
        s1 += __shfl_xor_sync(0xffffffffu, s1, 1);
        s1 += __shfl_xor_sync(0xffffffffu, s1, 2);
        l0 = l0 * al0 + s0;
        l1 = l1 * al1 + s1;

#pragma unroll
        for (int j = 0; j < 8; j++) {
            o[j][0] *= al0; o[j][1] *= al0;
            o[j][2] *= al1; o[j][3] *= al1;
        }

        // ---- O += P @ V ----
        {
            const unsigned vb = vbase0 + cur * 9216;
#pragma unroll
            for (int u = 0; u < 4; u++) {
                unsigned pa[4];
                pa[0] = f2h2(c[2 * u][0], c[2 * u][1]);
                pa[1] = f2h2(c[2 * u][2], c[2 * u][3]);
                pa[2] = f2h2(c[2 * u + 1][0], c[2 * u + 1][1]);
                pa[3] = f2h2(c[2 * u + 1][2], c[2 * u + 1][3]);
#pragma unroll
                for (int j2 = 0; j2 < 4; j2++) {
                    unsigned b0, b1, b2, b3;
                    ldsm4t(b0, b1, b2, b3, vb + u * 2304 + j2 * 32);
                    mma16816(o[2 * j2],     pa, b0, b1);
                    mma16816(o[2 * j2 + 1], pa, b2, b3);
                }
            }
        }
        __syncthreads();
    }

    float inv0 = 1.f / l0, inv1 = 1.f / l1;
    __half* outp = g_ao16 + (size_t)(bx * 128) * CDIM + head * 64;
#pragma unroll
    for (int j = 0; j < 8; j++) {
        int col = 8 * j + 2 * t;
        *(__half2*)&outp[(size_t)r0 * CDIM + col] =
            __floats2half2_rn(o[j][0] * inv0, o[j][1] * inv0);
        *(__half2*)&outp[(size_t)r1 * CDIM + col] =
            __floats2half2_rn(o[j][2] * inv1, o[j][3] * inv1);
    }
}

// ---------------------------------------------------------------------------
extern "C" void kernel_launch(void* const* d_in, const int* in_sizes, int n_in,
                              void* d_out, int out_size) {
    const float* x      = (const float*)d_in[0];
    const float* qkv_w  = (const float*)d_in[1];
    const float* qkv_b  = (const float*)d_in[2];
    const float* proj_w = (const float*)d_in[3];
    const float* proj_b = (const float*)d_in[4];
    const float* rph    = (const float*)d_in[5];
    const float* rpw    = (const float*)d_in[6];
    float* out = (float*)d_out;

    const int GEMM_SMEM  = 20480 * 2;   // 40960 B
    const int FLASH_SMEM = 46080 * 2;   // 92160 B
    cudaFuncSetAttribute(flash_attn, cudaFuncAttributeMaxDynamicSharedMemorySize, FLASH_SMEM);

    conv_x_kernel<<<(NQ * CDIM / 4 + 255) / 256, 256>>>(x);
    transpose_qkv_kernel<<<dim3(72, 24), dim3(32, 8)>>>(qkv_w);
    transpose_proj_kernel<<<dim3(24, 24), dim3(32, 8)>>>(proj_w);
    qkv_hgemm16<<<dim3(18, 32), 256, GEMM_SMEM>>>(qkv_b);
    flash_attn<<<dim3(32, 12), 256, FLASH_SMEM>>>(rph, rpw);
    proj_hgemm16<<<dim3(6, 32), 256, GEMM_SMEM>>>(proj_b, out);
}

// round 10
// speedup vs baseline: 7.1284x; 1.0472x over previous
#include <cuda_runtime.h>
#include <cuda_fp16.h>

// SAM Vision Attention: B=1, H=W=64, N=4096, C=768, nh=12, hd=64
// R10: qkv/proj GEMMs switch scalar LDS fragment loads -> ldmatrix.x4 and
//      force 2 CTAs/SM via __launch_bounds__(256,2). flash_attn unchanged (R9).

#define NH 12
#define NQ 4096
#define HD 64
#define CDIM 768
#define L2E 1.44269504f
#define SCALE_L2E (0.125f * 1.44269504f)   // 64^-0.5 * log2(e), folded into k

__device__ __half g_q16[NH * NQ * HD];
__device__ __half g_k16[NH * NQ * HD];        // pre-scaled by SCALE_L2E
__device__ __half g_v16[NH * NQ * HD];
__device__ __half g_ao16[NQ * CDIM];          // attention output (proj A input)
__device__ __half g_x16[NQ * CDIM];           // x in fp16
__device__ __half g_wqkvT[3 * CDIM * CDIM];   // qkv_w^T  [2304][768] fp16
__device__ __half g_wprojT[CDIM * CDIM];      // proj_w^T [768][768] fp16

// ---------------------------------------------------------------------------
// helpers
// ---------------------------------------------------------------------------
__device__ __forceinline__ void mma16816(float* c, const unsigned* a,
                                         unsigned b0, unsigned b1) {
    asm volatile(
        "mma.sync.aligned.m16n8k16.row.col.f32.f16.f16.f32 "
        "{%0,%1,%2,%3}, {%4,%5,%6,%7}, {%8,%9}, {%0,%1,%2,%3};\n"
        : "+f"(c[0]), "+f"(c[1]), "+f"(c[2]), "+f"(c[3])
        : "r"(a[0]), "r"(a[1]), "r"(a[2]), "r"(a[3]), "r"(b0), "r"(b1));
}

__device__ __forceinline__ unsigned f2h2(float x, float y) {
    __half2 h = __floats2half2_rn(x, y);
    return *(unsigned*)&h;
}

__device__ __forceinline__ float ex2f(float x) {
    float y;
    asm("ex2.approx.f32 %0, %1;" : "=f"(y) : "f"(x));
    return y;
}

__device__ __forceinline__ void cp_async16(void* dst, const void* src) {
    unsigned d = (unsigned)__cvta_generic_to_shared(dst);
    asm volatile("cp.async.cg.shared.global [%0], [%1], 16;\n" :: "r"(d), "l"(src));
}
#define CP_COMMIT asm volatile("cp.async.commit_group;\n")
#define CP_WAIT(n) asm volatile("cp.async.wait_group %0;\n" :: "n"(n))

__device__ __forceinline__ void ldsm4(unsigned& r0, unsigned& r1, unsigned& r2,
                                      unsigned& r3, unsigned a) {
    asm volatile("ldmatrix.sync.aligned.m8n8.x4.shared.b16 {%0,%1,%2,%3}, [%4];"
                 : "=r"(r0), "=r"(r1), "=r"(r2), "=r"(r3) : "r"(a));
}
__device__ __forceinline__ void ldsm4t(unsigned& r0, unsigned& r1, unsigned& r2,
                                       unsigned& r3, unsigned a) {
    asm volatile("ldmatrix.sync.aligned.m8n8.x4.trans.shared.b16 {%0,%1,%2,%3}, [%4];"
                 : "=r"(r0), "=r"(r1), "=r"(r2), "=r"(r3) : "r"(a));
}

// ---------------------------------------------------------------------------
// one-time conversion kernels (globals referenced from device code only)
// ---------------------------------------------------------------------------
__global__ void conv_x_kernel(const float* __restrict__ X) {
    int i = blockIdx.x * 256 + threadIdx.x;
    if (i < NQ * CDIM / 4) {
        float4 v = ((const float4*)X)[i];
        __half2* o = (__half2*)(g_x16 + i * 4);
        o[0] = __floats2half2_rn(v.x, v.y);
        o[1] = __floats2half2_rn(v.z, v.w);
    }
}

__global__ void transpose_qkv_kernel(const float* __restrict__ W) {
    __shared__ float tile[32][33];
    int bn = blockIdx.x * 32, bk = blockIdx.y * 32;
    int tx = threadIdx.x, ty = threadIdx.y;
#pragma unroll
    for (int i = 0; i < 32; i += 8)
        tile[ty + i][tx] = W[(size_t)(bk + ty + i) * 2304 + bn + tx];
    __syncthreads();
#pragma unroll
    for (int i = 0; i < 32; i += 8)
        g_wqkvT[(size_t)(bn + ty + i) * 768 + bk + tx] = __float2half(tile[tx][ty + i]);
}

__global__ void transpose_proj_kernel(const float* __restrict__ W) {
    __shared__ float tile[32][33];
    int bn = blockIdx.x * 32, bk = blockIdx.y * 32;
    int tx = threadIdx.x, ty = threadIdx.y;
#pragma unroll
    for (int i = 0; i < 32; i += 8)
        tile[ty + i][tx] = W[(size_t)(bk + ty + i) * 768 + bn + tx];
    __syncthreads();
#pragma unroll
    for (int i = 0; i < 32; i += 8)
        g_wprojT[(size_t)(bn + ty + i) * 768 + bk + tx] = __float2half(tile[tx][ty + i]);
}

// ---------------------------------------------------------------------------
// Shared fp16 HMMA GEMM body: BM=BN=128, BK=32, 8 warps, cp.async double
// buffer, ldmatrix.x4 fragment loads. A [M][768], BT [N][768], k-contiguous.
// Pitch 40 halves = 80 bytes.
// ---------------------------------------------------------------------------
struct GAcc { float c[2][8][4]; };

__device__ __forceinline__ void hgemm_body(const __half* __restrict__ A,
                                           const __half* __restrict__ BT,
                                           int bm, int bn, __half* As, __half* Bs,
                                           GAcc& F) {
    const int tid = threadIdx.x;
    const int w = tid >> 5, lane = tid & 31;
    const int m0 = (w >> 1) * 32, n0 = (w & 1) * 64;
    const int mat = lane >> 3, mr = lane & 7;

    // ldmatrix per-lane constants (bytes), pitch 80:
    // A frag (m16k16): mat0 rows+0 k+0 | mat1 rows+8 k+0 | mat2 rows+0 k+16B | mat3 rows+8 k+16B
    const unsigned aconst = ((mat & 1) * 8 + mr) * 80 + (mat >> 1) * 16;
    // B frag pair (n16k16): mat0 n+0 k+0 | mat1 n+0 k+16B | mat2 n+8 k+0 | mat3 n+8 k+16B
    const unsigned bconst = ((mat >> 1) * 8 + mr) * 80 + (mat & 1) * 16;
    const unsigned abase = (unsigned)__cvta_generic_to_shared(As) + m0 * 80 + aconst;
    const unsigned bbase = (unsigned)__cvta_generic_to_shared(Bs) + n0 * 80 + bconst;

#pragma unroll
    for (int mi = 0; mi < 2; mi++)
#pragma unroll
        for (int nj = 0; nj < 8; nj++)
#pragma unroll
            for (int e = 0; e < 4; e++) F.c[mi][nj][e] = 0.f;

#pragma unroll
    for (int i = 0; i < 2; i++) {
        int cdx = tid + i * 256;
        int row = cdx >> 2, off = (cdx & 3) * 8;
        cp_async16(As + row * 40 + off, A + (size_t)(bm + row) * 768 + off);
        cp_async16(Bs + row * 40 + off, BT + (size_t)(bn + row) * 768 + off);
    }
    CP_COMMIT;

    for (int kt = 0; kt < 24; kt++) {
        const int cur = kt & 1;
        if (kt < 23) {
            int k0 = (kt + 1) * 32;
            __half* dA = As + (cur ^ 1) * 5120;
            __half* dB = Bs + (cur ^ 1) * 5120;
#pragma unroll
            for (int i = 0; i < 2; i++) {
                int cdx = tid + i * 256;
                int row = cdx >> 2, off = (cdx & 3) * 8;
                cp_async16(dA + row * 40 + off, A + (size_t)(bm + row) * 768 + k0 + off);
                cp_async16(dB + row * 40 + off, BT + (size_t)(bn + row) * 768 + k0 + off);
            }
            CP_COMMIT;
            CP_WAIT(1);
        } else {
            CP_WAIT(0);
        }
        __syncthreads();

        const unsigned ab = abase + cur * 10240;
        const unsigned bb = bbase + cur * 10240;
#pragma unroll
        for (int ks = 0; ks < 2; ks++) {
            unsigned a[2][4], b[8][2];
#pragma unroll
            for (int mi = 0; mi < 2; mi++)
                ldsm4(a[mi][0], a[mi][1], a[mi][2], a[mi][3],
                      ab + mi * (16 * 80) + ks * 32);
#pragma unroll
            for (int nj2 = 0; nj2 < 4; nj2++)
                ldsm4(b[2 * nj2][0], b[2 * nj2][1], b[2 * nj2 + 1][0], b[2 * nj2 + 1][1],
                      bb + nj2 * (16 * 80) + ks * 32);
#pragma unroll
            for (int mi = 0; mi < 2; mi++)
#pragma unroll
                for (int nj = 0; nj < 8; nj++)
                    mma16816(F.c[mi][nj], a[mi], b[nj][0], b[nj][1]);
        }
        __syncthreads();
    }
}

// ---------------------------------------------------------------------------
// QKV GEMM: M=4096, N=2304. Epilogue scatters q/k/v (k folded with SCALE_L2E).
// ---------------------------------------------------------------------------
__global__ __launch_bounds__(256, 2) void qkv_hgemm16(const float* __restrict__ bias) {
    extern __shared__ __half smq[];
    const int bm = blockIdx.y * 128, bn = blockIdx.x * 128;
    const int tid = threadIdx.x;
    const int w = tid >> 5, lane = tid & 31;
    const int g = lane >> 2, t = lane & 3;
    const int m0 = (w >> 1) * 32, n0 = (w & 1) * 64;

    GAcc F;
    hgemm_body(g_x16, g_wqkvT, bm, bn, smq, smq + 10240, F);

#pragma unroll
    for (int mi = 0; mi < 2; mi++)
#pragma unroll
        for (int nj = 0; nj < 8; nj++)
#pragma unroll
            for (int e = 0; e < 4; e++) {
                int row = bm + m0 + mi * 16 + g + (e >> 1) * 8;
                int col = bn + n0 + nj * 8 + 2 * t + (e & 1);
                float val = F.c[mi][nj][e] + bias[col];
                int which = col / 768;
                int rem = col - which * 768;
                int head = rem >> 6, d = rem & 63;
                size_t off = ((size_t)head * NQ + row) * HD + d;
                if (which == 0) g_q16[off] = __float2half(val);
                else if (which == 1) g_k16[off] = __float2half(val * SCALE_L2E);
                else g_v16[off] = __float2half(val);
            }
}

// ---------------------------------------------------------------------------
// proj GEMM: M=4096, N=768.
// ---------------------------------------------------------------------------
__global__ __launch_bounds__(256, 2) void proj_hgemm16(const float* __restrict__ bias,
                                                       float* __restrict__ out) {
    extern __shared__ __half smp[];
    const int bm = blockIdx.y * 128, bn = blockIdx.x * 128;
    const int tid = threadIdx.x;
    const int w = tid >> 5, lane = tid & 31;
    const int g = lane >> 2, t = lane & 3;
    const int m0 = (w >> 1) * 32, n0 = (w & 1) * 64;

    GAcc F;
    hgemm_body(g_ao16, g_wprojT, bm, bn, smp, smp + 10240, F);

#pragma unroll
    for (int mi = 0; mi < 2; mi++)
#pragma unroll
        for (int nj = 0; nj < 8; nj++)
#pragma unroll
            for (int e2 = 0; e2 < 2; e2++) {
                int row = bm + m0 + mi * 16 + g + e2 * 8;
                int col = bn + n0 + nj * 8 + 2 * t;
                float2 v;
                v.x = F.c[mi][nj][e2 * 2 + 0] + bias[col];
                v.y = F.c[mi][nj][e2 * 2 + 1] + bias[col + 1];
                *(float2*)&out[(size_t)row * 768 + col] = v;
            }
}

// ---------------------------------------------------------------------------
// Flash attention (validated R9): 128 queries / CTA, 8 warps, fused rel-bias
// prologue, ldmatrix fragments, base-2 online softmax.
// ---------------------------------------------------------------------------
__global__ __launch_bounds__(256, 2) void flash_attn(const float* __restrict__ rph,
                                                     const float* __restrict__ rpw) {
    extern __shared__ __half smd[];
    __half* Qs  = smd;                 // [128][72]
    __half* Ksh = smd + 9216;          // 2 x [64][72]
    __half* Vsh = smd + 18432;         // 2 x [64][72]
    __half* RWs = smd + 27648;         // [128][72]  (xL2E)
    __half* RHs = smd + 36864;         // [128][72]  (xL2E)

    const int bx = blockIdx.x;
    const int head = blockIdx.y;
    const int qh0 = bx * 2;
    const int tid  = threadIdx.x;
    const int w    = tid >> 5;
    const int lane = tid & 31;
    const int g    = lane >> 2;
    const int t    = lane & 3;
    const int r0 = 16 * w + g;
    const int r1 = r0 + 8;

    const size_t qbase = ((size_t)head * NQ + bx * 128) * HD;
    const size_t hbase = (size_t)head * NQ * HD;

    const int mat = lane >> 3, mr = lane & 7;
    const unsigned smem_u32 = (unsigned)__cvta_generic_to_shared(smd);
    const unsigned kconst = ((mat >> 1) * 8 + mr) * 144 + (mat & 1) * 16;
    const unsigned vconst = ((mat & 1) * 8 + mr) * 144 + (mat >> 1) * 16;
    const unsigned kbase0 = smem_u32 + 9216 * 2 + kconst;
    const unsigned vbase0 = smem_u32 + 18432 * 2 + vconst;

    // ---- prologue phase 1: load Q, Bh (two tables), Bw ----
    {
        __half* Bh = smd + 9216;       // [2][64][72]
        __half* Bw = smd + 18432;      // [128][72], row 127 = 0
        const unsigned* gq = (const unsigned*)(g_q16 + qbase);
        for (int i = tid; i < 4096; i += 256) {
            int r = i >> 5, c2 = i & 31;
            *(unsigned*)&Qs[r * 72 + c2 * 2] = gq[i];
        }
        for (int i = tid; i < 8192; i += 256) {
            int h = i >> 12, j = i & 4095;
            int kh = j >> 6, c = j & 63;
            Bh[h * 4608 + kh * 72 + c] = __float2half(rph[(qh0 + h - kh + 63) * 64 + c]);
        }
        for (int i = tid; i < 127 * 64; i += 256) {
            int r = i >> 6, c = i & 63;
            Bw[r * 72 + c] = __float2half(rpw[i]);
        }
        if (tid < 64) Bw[127 * 72 + tid] = __float2half(0.f);
    }
    __syncthreads();

    unsigned qa[4][4];
#pragma unroll
    for (int u = 0; u < 4; u++) {
        int d = 16 * u + 2 * t;
        qa[u][0] = *(const unsigned*)&Qs[r0 * 72 + d];
        qa[u][1] = *(const unsigned*)&Qs[r1 * 72 + d];
        qa[u][2] = *(const unsigned*)&Qs[r0 * 72 + d + 8];
        qa[u][3] = *(const unsigned*)&Qs[r1 * 72 + d + 8];
    }

    // ---- prologue phase 2: RH = Q @ Bh[w>>2]^T ----
    {
        float ch[8][4];
#pragma unroll
        for (int j = 0; j < 8; j++)
#pragma unroll
            for (int e = 0; e < 4; e++) ch[j][e] = 0.f;
        const unsigned bhb = smem_u32 + (9216 + (w >> 2) * 4608) * 2 + kconst;
#pragma unroll
        for (int u = 0; u < 4; u++)
#pragma unroll
            for (int j2 = 0; j2 < 4; j2++) {
                unsigned b0, b1, b2, b3;
                ldsm4(b0, b1, b2, b3, bhb + j2 * 2304 + u * 32);
                mma16816(ch[2 * j2],     qa[u], b0, b1);
                mma16816(ch[2 * j2 + 1], qa[u], b2, b3);
            }
#pragma unroll
        for (int j = 0; j < 8; j++) {
            int col = 8 * j + 2 * t;
            *(unsigned*)&RHs[r0 * 72 + col] = f2h2(ch[j][0] * L2E, ch[j][1] * L2E);
            *(unsigned*)&RHs[r1 * 72 + col] = f2h2(ch[j][2] * L2E, ch[j][3] * L2E);
        }
    }

    // ---- prologue phase 3: P = Q @ Bw^T, gather RWs ----
    {
        float cp[16][4];
#pragma unroll
        for (int j = 0; j < 16; j++)
#pragma unroll
            for (int e = 0; e < 4; e++) cp[j][e] = 0.f;
        const unsigned bwb = smem_u32 + 18432 * 2 + kconst;
#pragma unroll
        for (int u = 0; u < 4; u++)
#pragma unroll
            for (int j2 = 0; j2 < 8; j2++) {
                unsigned b0, b1, b2, b3;
                ldsm4(b0, b1, b2, b3, bwb + j2 * 2304 + u * 32);
                mma16816(cp[2 * j2],     qa[u], b0, b1);
                mma16816(cp[2 * j2 + 1], qa[u], b2, b3);
            }
        __syncthreads();

        __half* Psm = smd + 9216;      // [128][136]
#pragma unroll
        for (int nj = 0; nj < 16; nj++) {
            int col = 8 * nj + 2 * t;
            *(unsigned*)&Psm[r0 * 136 + col] = f2h2(cp[nj][0] * L2E, cp[nj][1] * L2E);
            *(unsigned*)&Psm[r1 * 136 + col] = f2h2(cp[nj][2] * L2E, cp[nj][3] * L2E);
        }
        __syncthreads();

        for (int i = tid; i < 8192; i += 256) {
            int q = i >> 6, kw = i & 63;
            RWs[q * 72 + kw] = Psm[q * 136 + ((q & 63) - kw + 63)];
        }
    }
    __syncthreads();

    // ---- prefetch key tile 0 ----
    {
        const __half* gk = g_k16 + hbase;
        const __half* gv = g_v16 + hbase;
#pragma unroll
        for (int i = 0; i < 2; i++) {
            int c = tid + i * 256;
            int key = c >> 3, off = (c & 7) * 8;
            cp_async16(&Ksh[key * 72 + off], gk + c * 8);
            cp_async16(&Vsh[key * 72 + off], gv + c * 8);
        }
        CP_COMMIT;
    }

    float o[8][4];
#pragma unroll
    for (int j = 0; j < 8; j++)
#pragma unroll
        for (int e = 0; e < 4; e++) o[j][e] = 0.f;
    float m0 = -1e30f, m1 = -1e30f, l0 = 0.f, l1 = 0.f;

    for (int kt = 0; kt < 64; kt++) {
        const int cur = kt & 1;
        if (kt < 63) {
            const __half* gk = g_k16 + hbase + (size_t)(kt + 1) * 4096;
            const __half* gv = g_v16 + hbase + (size_t)(kt + 1) * 4096;
            __half* dk = Ksh + (cur ^ 1) * 4608;
            __half* dv = Vsh + (cur ^ 1) * 4608;
#pragma unroll
            for (int i = 0; i < 2; i++) {
                int c = tid + i * 256;
                int key = c >> 3, off = (c & 7) * 8;
                cp_async16(&dk[key * 72 + off], gk + c * 8);
                cp_async16(&dv[key * 72 + off], gv + c * 8);
            }
            CP_COMMIT;
            CP_WAIT(1);
        } else {
            CP_WAIT(0);
        }
        __syncthreads();

        float c[8][4];
#pragma unroll
        for (int j = 0; j < 8; j++)
#pragma unroll
            for (int e = 0; e < 4; e++) c[j][e] = 0.f;
        {
            const unsigned kb = kbase0 + cur * 9216;
#pragma unroll
            for (int u = 0; u < 4; u++) {
#pragma unroll
                for (int j2 = 0; j2 < 4; j2++) {
                    unsigned b0, b1, b2, b3;
                    ldsm4(b0, b1, b2, b3, kb + j2 * 2304 + u * 32);
                    mma16816(c[2 * j2],     qa[u], b0, b1);
                    mma16816(c[2 * j2 + 1], qa[u], b2, b3);
                }
            }
        }

        float rh0 = __half2float(RHs[r0 * 72 + kt]);
        float rh1 = __half2float(RHs[r1 * 72 + kt]);
#pragma unroll
        for (int j = 0; j < 8; j++) {
            int col = 8 * j + 2 * t;
            float2 w0 = __half22float2(*(const __half2*)&RWs[r0 * 72 + col]);
            float2 w1 = __half22float2(*(const __half2*)&RWs[r1 * 72 + col]);
            c[j][0] += rh0 + w0.x;
            c[j][1] += rh0 + w0.y;
            c[j][2] += rh1 + w1.x;
            c[j][3] += rh1 + w1.y;
        }

        float mx0 = -1e30f, mx1 = -1e30f;
#pragma unroll
        for (int j = 0; j < 8; j++) {
            mx0 = fmaxf(mx0, fmaxf(c[j][0], c[j][1]));
            mx1 = fmaxf(mx1, fmaxf(c[j][2], c[j][3]));
        }
        mx0 = fmaxf(mx0, __shfl_xor_sync(0xffffffffu, mx0, 1));
        mx0 = fmaxf(mx0, __shfl_xor_sync(0xffffffffu, mx0, 2));
        mx1 = fmaxf(mx1, __shfl_xor_sync(0xffffffffu, mx1, 1));
        mx1 = fmaxf(mx1, __shfl_xor_sync(0xffffffffu, mx1, 2));

        float mn0 = fmaxf(m0, mx0), mn1 = fmaxf(m1, mx1);
        float al0 = ex2f(m0 - mn0), al1 = ex2f(m1 - mn1);
        m0 = mn0; m1 = mn1;

        float s0 = 0.f, s1 = 0.f;
#pragma unroll
        for (int j = 0; j < 8; j++) {
            c[j][0] = ex2f(c[j][0] - mn0); s0 += c[j][0];
            c[j][1] = ex2f(c[j][1] - mn0); s0 += c[j][1];
            c[j][2] = ex2f(c[j][2] - mn1); s1 += c[j][2];
            c[j][3] = ex2f(c[j][3] - mn1); s1 += c[j][3];
        }
        s0 += __shfl_xor_sync(0xffffffffu, s0, 1);
        s0 += __shfl_xor_sync(0xffffffffu, s0, 2);
        s1 += __shfl_xor_sync(0xffffffffu, s1, 1);
        s1 += __shfl_xor_sync(0xffffffffu, s1, 2);
        l0 = l0 * al0 + s0;
        l1 = l1 * al1 + s1;

#pragma unroll
        for (int j = 0; j < 8; j++) {
            o[j][0] *= al0; o[j][1] *= al0;
            o[j][2] *= al1; o[j][3] *= al1;
        }

        {
            const unsigned vb = vbase0 + cur * 9216;
#pragma unroll
            for (int u = 0; u < 4; u++) {
                unsigned pa[4];
                pa[0] = f2h2(c[2 * u][0], c[2 * u][1]);
                pa[1] = f2h2(c[2 * u][2], c[2 * u][3]);
                pa[2] = f2h2(c[2 * u + 1][0], c[2 * u + 1][1]);
                pa[3] = f2h2(c[2 * u + 1][2], c[2 * u + 1][3]);
#pragma unroll
                for (int j2 = 0; j2 < 4; j2++) {
                    unsigned b0, b1, b2, b3;
                    ldsm4t(b0, b1, b2, b3, vb + u * 2304 + j2 * 32);
                    mma16816(o[2 * j2],     pa, b0, b1);
                    mma16816(o[2 * j2 + 1], pa, b2, b3);
                }
            }
        }
        __syncthreads();
    }

    float inv0 = 1.f / l0, inv1 = 1.f / l1;
    __half* outp = g_ao16 + (size_t)(bx * 128) * CDIM + head * 64;
#pragma unroll
    for (int j = 0; j < 8; j++) {
        int col = 8 * j + 2 * t;
        *(__half2*)&outp[(size_t)r0 * CDIM + col] =
            __floats2half2_rn(o[j][0] * inv0, o[j][1] * inv0);
        *(__half2*)&outp[(size_t)r1 * CDIM + col] =
            __floats2half2_rn(o[j][2] * inv1, o[j][3] * inv1);
    }
}

// ---------------------------------------------------------------------------
extern "C" void kernel_launch(void* const* d_in, const int* in_sizes, int n_in,
                              void* d_out, int out_size) {
    const float* x      = (const float*)d_in[0];
    const float* qkv_w  = (const float*)d_in[1];
    const float* qkv_b  = (const float*)d_in[2];
    const float* proj_w = (const float*)d_in[3];
    const float* proj_b = (const float*)d_in[4];
    const float* rph    = (const float*)d_in[5];
    const float* rpw    = (const float*)d_in[6];
    float* out = (float*)d_out;

    const int GEMM_SMEM  = 20480 * 2;   // 40960 B
    const int FLASH_SMEM = 46080 * 2;   // 92160 B
    cudaFuncSetAttribute(flash_attn, cudaFuncAttributeMaxDynamicSharedMemorySize, FLASH_SMEM);

    conv_x_kernel<<<(NQ * CDIM / 4 + 255) / 256, 256>>>(x);
    transpose_qkv_kernel<<<dim3(72, 24), dim3(32, 8)>>>(qkv_w);
    transpose_proj_kernel<<<dim3(24, 24), dim3(32, 8)>>>(proj_w);
    qkv_hgemm16<<<dim3(18, 32), 256, GEMM_SMEM>>>(qkv_b);
    flash_attn<<<dim3(32, 12), 256, FLASH_SMEM>>>(rph, rpw);
    proj_hgemm16<<<dim3(6, 32), 256, GEMM_SMEM>>>(proj_b, out);
}

// round 11
// speedup vs baseline: 7.6162x; 1.0684x over previous
#include <cuda_runtime.h>
#include <cuda_fp16.h>

// SAM Vision Attention: B=1, H=W=64, N=4096, C=768, nh=12, hd=64
// R11: qkv/proj GEMMs -> 3-stage cp.async pipeline (prefetch distance 2,
//      one __syncthreads per k-tile) + half2 epilogue stores in qkv.
//      flash_attn unchanged (validated R9/R10).

#define NH 12
#define NQ 4096
#define HD 64
#define CDIM 768
#define L2E 1.44269504f
#define SCALE_L2E (0.125f * 1.44269504f)   // 64^-0.5 * log2(e), folded into k

__device__ __half g_q16[NH * NQ * HD];
__device__ __half g_k16[NH * NQ * HD];        // pre-scaled by SCALE_L2E
__device__ __half g_v16[NH * NQ * HD];
__device__ __half g_ao16[NQ * CDIM];          // attention output (proj A input)
__device__ __half g_x16[NQ * CDIM];           // x in fp16
__device__ __half g_wqkvT[3 * CDIM * CDIM];   // qkv_w^T  [2304][768] fp16
__device__ __half g_wprojT[CDIM * CDIM];      // proj_w^T [768][768] fp16

// ---------------------------------------------------------------------------
// helpers
// ---------------------------------------------------------------------------
__device__ __forceinline__ void mma16816(float* c, const unsigned* a,
                                         unsigned b0, unsigned b1) {
    asm volatile(
        "mma.sync.aligned.m16n8k16.row.col.f32.f16.f16.f32 "
        "{%0,%1,%2,%3}, {%4,%5,%6,%7}, {%8,%9}, {%0,%1,%2,%3};\n"
        : "+f"(c[0]), "+f"(c[1]), "+f"(c[2]), "+f"(c[3])
        : "r"(a[0]), "r"(a[1]), "r"(a[2]), "r"(a[3]), "r"(b0), "r"(b1));
}

__device__ __forceinline__ unsigned f2h2(float x, float y) {
    __half2 h = __floats2half2_rn(x, y);
    return *(unsigned*)&h;
}

__device__ __forceinline__ float ex2f(float x) {
    float y;
    asm("ex2.approx.f32 %0, %1;" : "=f"(y) : "f"(x));
    return y;
}

__device__ __forceinline__ void cp_async16(void* dst, const void* src) {
    unsigned d = (unsigned)__cvta_generic_to_shared(dst);
    asm volatile("cp.async.cg.shared.global [%0], [%1], 16;\n" :: "r"(d), "l"(src));
}
#define CP_COMMIT asm volatile("cp.async.commit_group;\n")
#define CP_WAIT(n) asm volatile("cp.async.wait_group %0;\n" :: "n"(n))

__device__ __forceinline__ void ldsm4(unsigned& r0, unsigned& r1, unsigned& r2,
                                      unsigned& r3, unsigned a) {
    asm volatile("ldmatrix.sync.aligned.m8n8.x4.shared.b16 {%0,%1,%2,%3}, [%4];"
                 : "=r"(r0), "=r"(r1), "=r"(r2), "=r"(r3) : "r"(a));
}
__device__ __forceinline__ void ldsm4t(unsigned& r0, unsigned& r1, unsigned& r2,
                                       unsigned& r3, unsigned a) {
    asm volatile("ldmatrix.sync.aligned.m8n8.x4.trans.shared.b16 {%0,%1,%2,%3}, [%4];"
                 : "=r"(r0), "=r"(r1), "=r"(r2), "=r"(r3) : "r"(a));
}

// ---------------------------------------------------------------------------
// one-time conversion kernels (globals referenced from device code only)
// ---------------------------------------------------------------------------
__global__ void conv_x_kernel(const float* __restrict__ X) {
    int i = blockIdx.x * 256 + threadIdx.x;
    if (i < NQ * CDIM / 4) {
        float4 v = ((const float4*)X)[i];
        __half2* o = (__half2*)(g_x16 + i * 4);
        o[0] = __floats2half2_rn(v.x, v.y);
        o[1] = __floats2half2_rn(v.z, v.w);
    }
}

__global__ void transpose_qkv_kernel(const float* __restrict__ W) {
    __shared__ float tile[32][33];
    int bn = blockIdx.x * 32, bk = blockIdx.y * 32;
    int tx = threadIdx.x, ty = threadIdx.y;
#pragma unroll
    for (int i = 0; i < 32; i += 8)
        tile[ty + i][tx] = W[(size_t)(bk + ty + i) * 2304 + bn + tx];
    __syncthreads();
#pragma unroll
    for (int i = 0; i < 32; i += 8)
        g_wqkvT[(size_t)(bn + ty + i) * 768 + bk + tx] = __float2half(tile[tx][ty + i]);
}

__global__ void transpose_proj_kernel(const float* __restrict__ W) {
    __shared__ float tile[32][33];
    int bn = blockIdx.x * 32, bk = blockIdx.y * 32;
    int tx = threadIdx.x, ty = threadIdx.y;
#pragma unroll
    for (int i = 0; i < 32; i += 8)
        tile[ty + i][tx] = W[(size_t)(bk + ty + i) * 768 + bn + tx];
    __syncthreads();
#pragma unroll
    for (int i = 0; i < 32; i += 8)
        g_wprojT[(size_t)(bn + ty + i) * 768 + bk + tx] = __float2half(tile[tx][ty + i]);
}

// ---------------------------------------------------------------------------
// Shared fp16 HMMA GEMM body: BM=BN=128, BK=32, 8 warps, 3-stage cp.async
// pipeline (prefetch distance 2), ldmatrix.x4 fragment loads.
// A [M][768], BT [N][768], k-contiguous. smem pitch 40 halves (80 B).
// smem: As 3 x 5120 halves at 0 | Bs 3 x 5120 halves at 15360.
// ---------------------------------------------------------------------------
struct GAcc { float c[2][8][4]; };

__device__ __forceinline__ void gemm_load_tile(const __half* __restrict__ A,
                                               const __half* __restrict__ BT,
                                               int bm, int bn, int k0,
                                               __half* dA, __half* dB, int tid) {
#pragma unroll
    for (int i = 0; i < 2; i++) {
        int cdx = tid + i * 256;
        int row = cdx >> 2, off = (cdx & 3) * 8;
        cp_async16(dA + row * 40 + off, A + (size_t)(bm + row) * 768 + k0 + off);
        cp_async16(dB + row * 40 + off, BT + (size_t)(bn + row) * 768 + k0 + off);
    }
    CP_COMMIT;
}

__device__ __forceinline__ void hgemm_body(const __half* __restrict__ A,
                                           const __half* __restrict__ BT,
                                           int bm, int bn, __half* As, __half* Bs,
                                           GAcc& F) {
    const int tid = threadIdx.x;
    const int w = tid >> 5, lane = tid & 31;
    const int m0 = (w >> 1) * 32, n0 = (w & 1) * 64;
    const int mat = lane >> 3, mr = lane & 7;

    const unsigned aconst = ((mat & 1) * 8 + mr) * 80 + (mat >> 1) * 16;
    const unsigned bconst = ((mat >> 1) * 8 + mr) * 80 + (mat & 1) * 16;
    const unsigned abase = (unsigned)__cvta_generic_to_shared(As) + m0 * 80 + aconst;
    const unsigned bbase = (unsigned)__cvta_generic_to_shared(Bs) + n0 * 80 + bconst;

#pragma unroll
    for (int mi = 0; mi < 2; mi++)
#pragma unroll
        for (int nj = 0; nj < 8; nj++)
#pragma unroll
            for (int e = 0; e < 4; e++) F.c[mi][nj][e] = 0.f;

    // prefetch tiles 0 and 1 (two commit groups)
    gemm_load_tile(A, BT, bm, bn, 0,  As,        Bs,        tid);
    gemm_load_tile(A, BT, bm, bn, 32, As + 5120, Bs + 5120, tid);

    for (int kt = 0; kt < 24; kt++) {
        const int cur = kt - (kt / 3) * 3;          // kt % 3
        if (kt < 23) { CP_WAIT(1); } else { CP_WAIT(0); }
        __syncthreads();     // tile kt visible to all; all reads of buffer
                             // (kt+2)%3 (tile kt-1) finished

        if (kt < 22) {
            int nxt = kt + 2;
            int buf = nxt - (nxt / 3) * 3;
            gemm_load_tile(A, BT, bm, bn, nxt * 32,
                           As + buf * 5120, Bs + buf * 5120, tid);
        }

        const unsigned ab = abase + cur * 10240;
        const unsigned bb = bbase + cur * 10240;
#pragma unroll
        for (int ks = 0; ks < 2; ks++) {
            unsigned a[2][4], b[8][2];
#pragma unroll
            for (int mi = 0; mi < 2; mi++)
                ldsm4(a[mi][0], a[mi][1], a[mi][2], a[mi][3],
                      ab + mi * (16 * 80) + ks * 32);
#pragma unroll
            for (int nj2 = 0; nj2 < 4; nj2++)
                ldsm4(b[2 * nj2][0], b[2 * nj2][1], b[2 * nj2 + 1][0], b[2 * nj2 + 1][1],
                      bb + nj2 * (16 * 80) + ks * 32);
#pragma unroll
            for (int mi = 0; mi < 2; mi++)
#pragma unroll
                for (int nj = 0; nj < 8; nj++)
                    mma16816(F.c[mi][nj], a[mi], b[nj][0], b[nj][1]);
        }
    }
    __syncthreads();
}

// ---------------------------------------------------------------------------
// QKV GEMM: M=4096, N=2304. half2 epilogue stores (col pairs 2t/2t+1 share
// head and adjacent d since d = (col mod 768) & 63 with col even).
// ---------------------------------------------------------------------------
__global__ __launch_bounds__(256, 2) void qkv_hgemm16(const float* __restrict__ bias) {
    extern __shared__ __half smq[];
    const int bm = blockIdx.y * 128, bn = blockIdx.x * 128;
    const int tid = threadIdx.x;
    const int w = tid >> 5, lane = tid & 31;
    const int g = lane >> 2, t = lane & 3;
    const int m0 = (w >> 1) * 32, n0 = (w & 1) * 64;

    GAcc F;
    hgemm_body(g_x16, g_wqkvT, bm, bn, smq, smq + 15360, F);

#pragma unroll
    for (int mi = 0; mi < 2; mi++)
#pragma unroll
        for (int nj = 0; nj < 8; nj++)
#pragma unroll
            for (int e2 = 0; e2 < 2; e2++) {
                int row = bm + m0 + mi * 16 + g + e2 * 8;
                int col = bn + n0 + nj * 8 + 2 * t;
                float v0 = F.c[mi][nj][e2 * 2 + 0] + bias[col];
                float v1 = F.c[mi][nj][e2 * 2 + 1] + bias[col + 1];
                int which = col / 768;
                int rem = col - which * 768;
                int head = rem >> 6, d = rem & 63;
                size_t off = ((size_t)head * NQ + row) * HD + d;
                if (which == 0)
                    *(__half2*)(g_q16 + off) = __floats2half2_rn(v0, v1);
                else if (which == 1)
                    *(__half2*)(g_k16 + off) =
                        __floats2half2_rn(v0 * SCALE_L2E, v1 * SCALE_L2E);
                else
                    *(__half2*)(g_v16 + off) = __floats2half2_rn(v0, v1);
            }
}

// ---------------------------------------------------------------------------
// proj GEMM: M=4096, N=768.
// ---------------------------------------------------------------------------
__global__ __launch_bounds__(256, 2) void proj_hgemm16(const float* __restrict__ bias,
                                                       float* __restrict__ out) {
    extern __shared__ __half smp[];
    const int bm = blockIdx.y * 128, bn = blockIdx.x * 128;
    const int tid = threadIdx.x;
    const int w = tid >> 5, lane = tid & 31;
    const int g = lane >> 2, t = lane & 3;
    const int m0 = (w >> 1) * 32, n0 = (w & 1) * 64;

    GAcc F;
    hgemm_body(g_ao16, g_wprojT, bm, bn, smp, smp + 15360, F);

#pragma unroll
    for (int mi = 0; mi < 2; mi++)
#pragma unroll
        for (int nj = 0; nj < 8; nj++)
#pragma unroll
            for (int e2 = 0; e2 < 2; e2++) {
                int row = bm + m0 + mi * 16 + g + e2 * 8;
                int col = bn + n0 + nj * 8 + 2 * t;
                float2 v;
                v.x = F.c[mi][nj][e2 * 2 + 0] + bias[col];
                v.y = F.c[mi][nj][e2 * 2 + 1] + bias[col + 1];
                *(float2*)&out[(size_t)row * 768 + col] = v;
            }
}

// ---------------------------------------------------------------------------
// Flash attention (validated R9/R10): 128 queries / CTA, 8 warps, fused
// rel-bias prologue, ldmatrix fragments, base-2 online softmax.
// ---------------------------------------------------------------------------
__global__ __launch_bounds__(256, 2) void flash_attn(const float* __restrict__ rph,
                                                     const float* __restrict__ rpw) {
    extern __shared__ __half smd[];
    __half* Qs  = smd;                 // [128][72]
    __half* Ksh = smd + 9216;          // 2 x [64][72]
    __half* Vsh = smd + 18432;         // 2 x [64][72]
    __half* RWs = smd + 27648;         // [128][72]  (xL2E)
    __half* RHs = smd + 36864;         // [128][72]  (xL2E)

    const int bx = blockIdx.x;
    const int head = blockIdx.y;
    const int qh0 = bx * 2;
    const int tid  = threadIdx.x;
    const int w    = tid >> 5;
    const int lane = tid & 31;
    const int g    = lane >> 2;
    const int t    = lane & 3;
    const int r0 = 16 * w + g;
    const int r1 = r0 + 8;

    const size_t qbase = ((size_t)head * NQ + bx * 128) * HD;
    const size_t hbase = (size_t)head * NQ * HD;

    const int mat = lane >> 3, mr = lane & 7;
    const unsigned smem_u32 = (unsigned)__cvta_generic_to_shared(smd);
    const unsigned kconst = ((mat >> 1) * 8 + mr) * 144 + (mat & 1) * 16;
    const unsigned vconst = ((mat & 1) * 8 + mr) * 144 + (mat >> 1) * 16;
    const unsigned kbase0 = smem_u32 + 9216 * 2 + kconst;
    const unsigned vbase0 = smem_u32 + 18432 * 2 + vconst;

    // ---- prologue phase 1: load Q, Bh (two tables), Bw ----
    {
        __half* Bh = smd + 9216;       // [2][64][72]
        __half* Bw = smd + 18432;      // [128][72], row 127 = 0
        const unsigned* gq = (const unsigned*)(g_q16 + qbase);
        for (int i = tid; i < 4096; i += 256) {
            int r = i >> 5, c2 = i & 31;
            *(unsigned*)&Qs[r * 72 + c2 * 2] = gq[i];
        }
        for (int i = tid; i < 8192; i += 256) {
            int h = i >> 12, j = i & 4095;
            int kh = j >> 6, c = j & 63;
            Bh[h * 4608 + kh * 72 + c] = __float2half(rph[(qh0 + h - kh + 63) * 64 + c]);
        }
        for (int i = tid; i < 127 * 64; i += 256) {
            int r = i >> 6, c = i & 63;
            Bw[r * 72 + c] = __float2half(rpw[i]);
        }
        if (tid < 64) Bw[127 * 72 + tid] = __float2half(0.f);
    }
    __syncthreads();

    unsigned qa[4][4];
#pragma unroll
    for (int u = 0; u < 4; u++) {
        int d = 16 * u + 2 * t;
        qa[u][0] = *(const unsigned*)&Qs[r0 * 72 + d];
        qa[u][1] = *(const unsigned*)&Qs[r1 * 72 + d];
        qa[u][2] = *(const unsigned*)&Qs[r0 * 72 + d + 8];
        qa[u][3] = *(const unsigned*)&Qs[r1 * 72 + d + 8];
    }

    // ---- prologue phase 2: RH = Q @ Bh[w>>2]^T ----
    {
        float ch[8][4];
#pragma unroll
        for (int j = 0; j < 8; j++)
#pragma unroll
            for (int e = 0; e < 4; e++) ch[j][e] = 0.f;
        const unsigned bhb = smem_u32 + (9216 + (w >> 2) * 4608) * 2 + kconst;
#pragma unroll
        for (int u = 0; u < 4; u++)
#pragma unroll
            for (int j2 = 0; j2 < 4; j2++) {
                unsigned b0, b1, b2, b3;
                ldsm4(b0, b1, b2, b3, bhb + j2 * 2304 + u * 32);
                mma16816(ch[2 * j2],     qa[u], b0, b1);
                mma16816(ch[2 * j2 + 1], qa[u], b2, b3);
            }
#pragma unroll
        for (int j = 0; j < 8; j++) {
            int col = 8 * j + 2 * t;
            *(unsigned*)&RHs[r0 * 72 + col] = f2h2(ch[j][0] * L2E, ch[j][1] * L2E);
            *(unsigned*)&RHs[r1 * 72 + col] = f2h2(ch[j][2] * L2E, ch[j][3] * L2E);
        }
    }

    // ---- prologue phase 3: P = Q @ Bw^T, gather RWs ----
    {
        float cp[16][4];
#pragma unroll
        for (int j = 0; j < 16; j++)
#pragma unroll
            for (int e = 0; e < 4; e++) cp[j][e] = 0.f;
        const unsigned bwb = smem_u32 + 18432 * 2 + kconst;
#pragma unroll
        for (int u = 0; u < 4; u++)
#pragma unroll
            for (int j2 = 0; j2 < 8; j2++) {
                unsigned b0, b1, b2, b3;
                ldsm4(b0, b1, b2, b3, bwb + j2 * 2304 + u * 32);
                mma16816(cp[2 * j2],     qa[u], b0, b1);
                mma16816(cp[2 * j2 + 1], qa[u], b2, b3);
            }
        __syncthreads();

        __half* Psm = smd + 9216;      // [128][136]
#pragma unroll
        for (int nj = 0; nj < 16; nj++) {
            int col = 8 * nj + 2 * t;
            *(unsigned*)&Psm[r0 * 136 + col] = f2h2(cp[nj][0] * L2E, cp[nj][1] * L2E);
            *(unsigned*)&Psm[r1 * 136 + col] = f2h2(cp[nj][2] * L2E, cp[nj][3] * L2E);
        }
        __syncthreads();

        for (int i = tid; i < 8192; i += 256) {
            int q = i >> 6, kw = i & 63;
            RWs[q * 72 + kw] = Psm[q * 136 + ((q & 63) - kw + 63)];
        }
    }
    __syncthreads();

    // ---- prefetch key tile 0 ----
    {
        const __half* gk = g_k16 + hbase;
        const __half* gv = g_v16 + hbase;
#pragma unroll
        for (int i = 0; i < 2; i++) {
            int c = tid + i * 256;
            int key = c >> 3, off = (c & 7) * 8;
            cp_async16(&Ksh[key * 72 + off], gk + c * 8);
            cp_async16(&Vsh[key * 72 + off], gv + c * 8);
        }
        CP_COMMIT;
    }

    float o[8][4];
#pragma unroll
    for (int j = 0; j < 8; j++)
#pragma unroll
        for (int e = 0; e < 4; e++) o[j][e] = 0.f;
    float m0 = -1e30f, m1 = -1e30f, l0 = 0.f, l1 = 0.f;

    for (int kt = 0; kt < 64; kt++) {
        const int cur = kt & 1;
        if (kt < 63) {
            const __half* gk = g_k16 + hbase + (size_t)(kt + 1) * 4096;
            const __half* gv = g_v16 + hbase + (size_t)(kt + 1) * 4096;
            __half* dk = Ksh + (cur ^ 1) * 4608;
            __half* dv = Vsh + (cur ^ 1) * 4608;
#pragma unroll
            for (int i = 0; i < 2; i++) {
                int c = tid + i * 256;
                int key = c >> 3, off = (c & 7) * 8;
                cp_async16(&dk[key * 72 + off], gk + c * 8);
                cp_async16(&dv[key * 72 + off], gv + c * 8);
            }
            CP_COMMIT;
            CP_WAIT(1);
        } else {
            CP_WAIT(0);
        }
        __syncthreads();

        float c[8][4];
#pragma unroll
        for (int j = 0; j < 8; j++)
#pragma unroll
            for (int e = 0; e < 4; e++) c[j][e] = 0.f;
        {
            const unsigned kb = kbase0 + cur * 9216;
#pragma unroll
            for (int u = 0; u < 4; u++) {
#pragma unroll
                for (int j2 = 0; j2 < 4; j2++) {
                    unsigned b0, b1, b2, b3;
                    ldsm4(b0, b1, b2, b3, kb + j2 * 2304 + u * 32);
                    mma16816(c[2 * j2],     qa[u], b0, b1);
                    mma16816(c[2 * j2 + 1], qa[u], b2, b3);
                }
            }
        }

        float rh0 = __half2float(RHs[r0 * 72 + kt]);
        float rh1 = __half2float(RHs[r1 * 72 + kt]);
#pragma unroll
        for (int j = 0; j < 8; j++) {
            int col = 8 * j + 2 * t;
            float2 w0 = __half22float2(*(const __half2*)&RWs[r0 * 72 + col]);
            float2 w1 = __half22float2(*(const __half2*)&RWs[r1 * 72 + col]);
            c[j][0] += rh0 + w0.x;
            c[j][1] += rh0 + w0.y;
            c[j][2] += rh1 + w1.x;
            c[j][3] += rh1 + w1.y;
        }

        float mx0 = -1e30f, mx1 = -1e30f;
#pragma unroll
        for (int j = 0; j < 8; j++) {
            mx0 = fmaxf(mx0, fmaxf(c[j][0], c[j][1]));
            mx1 = fmaxf(mx1, fmaxf(c[j][2], c[j][3]));
        }
        mx0 = fmaxf(mx0, __shfl_xor_sync(0xffffffffu, mx0, 1));
        mx0 = fmaxf(mx0, __shfl_xor_sync(0xffffffffu, mx0, 2));
        mx1 = fmaxf(mx1, __shfl_xor_sync(0xffffffffu, mx1, 1));
        mx1 = fmaxf(mx1, __shfl_xor_sync(0xffffffffu, mx1, 2));

        float mn0 = fmaxf(m0, mx0), mn1 = fmaxf(m1, mx1);
        float al0 = ex2f(m0 - mn0), al1 = ex2f(m1 - mn1);
        m0 = mn0; m1 = mn1;

        float s0 = 0.f, s1 = 0.f;
#pragma unroll
        for (int j = 0; j < 8; j++) {
            c[j][0] = ex2f(c[j][0] - mn0); s0 += c[j][0];
            c[j][1] = ex2f(c[j][1] - mn0); s0 += c[j][1];
            c[j][2] = ex2f(c[j][2] - mn1); s1 += c[j][2];
            c[j][3] = ex2f(c[j][3] - mn1); s1 += c[j][3];
        }
        s0 += __shfl_xor_sync(0xffffffffu, s0, 1);
        s0 += __shfl_xor_sync(0xffffffffu, s0, 2);
        s1 += __shfl_xor_sync(0xffffffffu, s1, 1);
        s1 += __shfl_xor_sync(0xffffffffu, s1, 2);
        l0 = l0 * al0 + s0;
        l1 = l1 * al1 + s1;

#pragma unroll
        for (int j = 0; j < 8; j++) {
            o[j][0] *= al0; o[j][1] *= al0;
            o[j][2] *= al1; o[j][3] *= al1;
        }

        {
            const unsigned vb = vbase0 + cur * 9216;
#pragma unroll
            for (int u = 0; u < 4; u++) {
                unsigned pa[4];
                pa[0] = f2h2(c[2 * u][0], c[2 * u][1]);
                pa[1] = f2h2(c[2 * u][2], c[2 * u][3]);
                pa[2] = f2h2(c[2 * u + 1][0], c[2 * u + 1][1]);
                pa[3] = f2h2(c[2 * u + 1][2], c[2 * u + 1][3]);
#pragma unroll
                for (int j2 = 0; j2 < 4; j2++) {
                    unsigned b0, b1, b2, b3;
                    ldsm4t(b0, b1, b2, b3, vb + u * 2304 + j2 * 32);
                    mma16816(o[2 * j2],     pa, b0, b1);
                    mma16816(o[2 * j2 + 1], pa, b2, b3);
                }
            }
        }
        __syncthreads();
    }

    float inv0 = 1.f / l0, inv1 = 1.f / l1;
    __half* outp = g_ao16 + (size_t)(bx * 128) * CDIM + head * 64;
#pragma unroll
    for (int j = 0; j < 8; j++) {
        int col = 8 * j + 2 * t;
        *(__half2*)&outp[(size_t)r0 * CDIM + col] =
            __floats2half2_rn(o[j][0] * inv0, o[j][1] * inv0);
        *(__half2*)&outp[(size_t)r1 * CDIM + col] =
            __floats2half2_rn(o[j][2] * inv1, o[j][3] * inv1);
    }
}

// ---------------------------------------------------------------------------
extern "C" void kernel_launch(void* const* d_in, const int* in_sizes, int n_in,
                              void* d_out, int out_size) {
    const float* x      = (const float*)d_in[0];
    const float* qkv_w  = (const float*)d_in[1];
    const float* qkv_b  = (const float*)d_in[2];
    const float* proj_w = (const float*)d_in[3];
    const float* proj_b = (const float*)d_in[4];
    const float* rph    = (const float*)d_in[5];
    const float* rpw    = (const float*)d_in[6];
    float* out = (float*)d_out;

    const int GEMM_SMEM  = 30720 * 2;   // 61440 B (3-stage double operand)
    const int FLASH_SMEM = 46080 * 2;   // 92160 B
    cudaFuncSetAttribute(qkv_hgemm16, cudaFuncAttributeMaxDynamicSharedMemorySize, GEMM_SMEM);
    cudaFuncSetAttribute(proj_hgemm16, cudaFuncAttributeMaxDynamicSharedMemorySize, GEMM_SMEM);
    cudaFuncSetAttribute(flash_attn, cudaFuncAttributeMaxDynamicSharedMemorySize, FLASH_SMEM);

    conv_x_kernel<<<(NQ * CDIM / 4 + 255) / 256, 256>>>(x);
    transpose_qkv_kernel<<<dim3(72, 24), dim3(32, 8)>>>(qkv_w);
    transpose_proj_kernel<<<dim3(24, 24), dim3(32, 8)>>>(proj_w);
    qkv_hgemm16<<<dim3(18, 32), 256, GEMM_SMEM>>>(qkv_b);
    flash_attn<<<dim3(32, 12), 256, FLASH_SMEM>>>(rph, rpw);
    proj_hgemm16<<<dim3(6, 32), 256, GEMM_SMEM>>>(proj_b, out);
}